// round 10
// baseline (speedup 1.0000x reference)
#include <cuda_runtime.h>
#include <cstdint>
#include <math.h>
#include <mma.h>

using namespace nvcuda;

// Problem constants
#define BB   2
#define TT   2048
#define DM   1024
#define NH   16
#define NG   4
#define DH   64
#define HPG  (NH / NG)          // 4
#define MTOT (BB * TT)          // 4096
#define KVD  (NG * DH)          // 256

#define TF32(x) wmma::__float_to_tf32(x)

// Scratch (no cudaMalloc allowed)
static __device__ float g_Q[(size_t)MTOT * DM];
static __device__ float g_K[(size_t)MTOT * KVD];
static __device__ float g_V[(size_t)MTOT * KVD];
static __device__ float g_Kp[(size_t)MTOT * KVD];   // rope'd, tf32, head-permuted
static __device__ float g_Vp[(size_t)MTOT * KVD];   // tf32, head-permuted
static __device__ float g_A[(size_t)MTOT * DM];

// ---------------------------------------------------------------------------
// helpers
// ---------------------------------------------------------------------------
__device__ __forceinline__ void cp16(void* s, const void* g) {
    unsigned int sa = (unsigned int)__cvta_generic_to_shared(s);
    asm volatile("cp.async.cg.shared.global [%0], [%1], 16;\n" :: "r"(sa), "l"(g));
}
__device__ __forceinline__ void cp_commit() { asm volatile("cp.async.commit_group;\n"); }
template<int N> __device__ __forceinline__ void cp_wait() {
    asm volatile("cp.async.wait_group %0;\n" :: "n"(N));
}

// mma.m16n8k8 tf32: D += A * B  (A row-major 16x8, B col-major 8x8)
__device__ __forceinline__ void mma16n8k8(
    float& d0, float& d1, float& d2, float& d3,
    float a0, float a1, float a2, float a3, float b0, float b1)
{
    unsigned int ua0 = __float_as_uint(a0), ua1 = __float_as_uint(a1);
    unsigned int ua2 = __float_as_uint(a2), ua3 = __float_as_uint(a3);
    unsigned int ub0 = __float_as_uint(b0), ub1 = __float_as_uint(b1);
    asm volatile(
        "mma.sync.aligned.m16n8k8.row.col.f32.tf32.tf32.f32 "
        "{%0,%1,%2,%3}, {%4,%5,%6,%7}, {%8,%9}, {%0,%1,%2,%3};"
        : "+f"(d0), "+f"(d1), "+f"(d2), "+f"(d3)
        : "r"(ua0), "r"(ua1), "r"(ua2), "r"(ua3), "r"(ub0), "r"(ub1));
}

// ---------------------------------------------------------------------------
// Shared GEMM core: 128x128 tile, 4 warps (2x2 of 64x64), 3-stage cp.async.
// Reads RAW fp32 A/B; rounds fragments to tf32 in-register (RNA) before mma,
// which is numerically identical to pre-rounded operand copies.
// ---------------------------------------------------------------------------
#define BK 16
#define LDA (BK + 4)
#define LDB (128 + 4)
#define GST 3
#define GSMEM ((GST * (128 * LDA + BK * LDB)) * 4)   // 56064 B

template<typename EPI>
__device__ __forceinline__ void gemm_core(
    const float* __restrict__ Ap, const float* __restrict__ Bp, int ldbg,
    const float* __restrict__ biasp, EPI epi)
{
    extern __shared__ float smem[];
    float* As = smem;
    float* Bs = smem + GST * 128 * LDA;

    int tid = threadIdx.x;
    int warp = tid >> 5;
    int wm = warp & 1;
    int wn = warp >> 1;

    wmma::fragment<wmma::accumulator, 16, 16, 8, float> acc[4][4];

    // bias -> accumulators (16 replicated rows staged in Bs)
    for (int i = tid; i < 16 * 128; i += 128) {
        int r = i >> 7, c = i & 127;
        Bs[r * LDB + c] = biasp[c];
    }
    __syncthreads();
#pragma unroll
    for (int i = 0; i < 4; i++)
#pragma unroll
        for (int j = 0; j < 4; j++)
            wmma::load_matrix_sync(acc[i][j], &Bs[wn * 64 + j * 16], LDB,
                                   wmma::mem_row_major);
    __syncthreads();

    const int NIT = DM / BK;

    auto issueG = [&](int it) {
        int s = it % GST, k0 = it * BK;
        float* as = &As[s * 128 * LDA];
        float* bs = &Bs[s * BK * LDB];
#pragma unroll
        for (int i = tid; i < 512; i += 128) {
            int r = i >> 2, c = (i & 3) << 2;
            cp16(&as[r * LDA + c], Ap + (size_t)r * DM + k0 + c);
        }
#pragma unroll
        for (int i = tid; i < 512; i += 128) {
            int r = i >> 5, c = (i & 31) << 2;
            cp16(&bs[r * LDB + c], Bp + (size_t)(k0 + r) * ldbg + c);
        }
        cp_commit();
    };

    issueG(0); issueG(1); issueG(2);

    for (int it = 0; it < NIT; it++) {
        if (it + 3 <= NIT) cp_wait<2>();
        else if (it + 2 <= NIT) cp_wait<1>();
        else cp_wait<0>();
        __syncthreads();
        int s = it % GST;
        const float* as = &As[s * 128 * LDA];
        const float* bs = &Bs[s * BK * LDB];
#pragma unroll
        for (int ks = 0; ks < BK; ks += 8) {
            wmma::fragment<wmma::matrix_a, 16, 16, 8, wmma::precision::tf32, wmma::row_major> af[4];
            wmma::fragment<wmma::matrix_b, 16, 16, 8, wmma::precision::tf32, wmma::row_major> bf[4];
#pragma unroll
            for (int i = 0; i < 4; i++) {
                wmma::load_matrix_sync(af[i], &as[(wm * 64 + i * 16) * LDA + ks], LDA);
                for (int t = 0; t < af[i].num_elements; t++)
                    af[i].x[t] = TF32(af[i].x[t]);
            }
#pragma unroll
            for (int j = 0; j < 4; j++) {
                wmma::load_matrix_sync(bf[j], &bs[ks * LDB + wn * 64 + j * 16], LDB);
                for (int t = 0; t < bf[j].num_elements; t++)
                    bf[j].x[t] = TF32(bf[j].x[t]);
            }
#pragma unroll
            for (int i = 0; i < 4; i++)
#pragma unroll
                for (int j = 0; j < 4; j++)
                    wmma::mma_sync(acc[i][j], af[i], bf[j], acc[i][j]);
        }
        __syncthreads();
        if (it + GST < NIT) issueG(it + GST);
    }

    epi(acc, wm, wn);
}

// fused QKV GEMM: bn 0..7 -> Q, 8..9 -> K, 10..11 -> V (tf32-rounded).
// Reads raw x / Wq / Wk / Wv / biases directly.
__global__ __launch_bounds__(128, 3) void gemm_qkv_kernel(
    const float* __restrict__ A,
    const float* __restrict__ Wq, const float* __restrict__ Wk,
    const float* __restrict__ Wv,
    const float* __restrict__ bq, const float* __restrict__ bk,
    const float* __restrict__ bv,
    float* __restrict__ Qo, float* __restrict__ Ko, float* __restrict__ Vo)
{
    int bn = blockIdx.x, bm = blockIdx.y;
    const float* Bw; const float* bias; float* Cb; int ldc, ldbg; bool rnd = false;
    if (bn < 8)       { Bw = Wq + bn * 128;        bias = bq + bn * 128;
                        Cb = Qo + bn * 128;        ldc = DM;  ldbg = DM;  }
    else if (bn < 10) { Bw = Wk + (bn - 8) * 128;  bias = bk + (bn - 8) * 128;
                        Cb = Ko + (bn - 8) * 128;  ldc = KVD; ldbg = KVD; }
    else              { Bw = Wv + (bn - 10) * 128; bias = bv + (bn - 10) * 128;
                        Cb = Vo + (bn - 10) * 128; ldc = KVD; ldbg = KVD; rnd = true; }

    gemm_core(A + (size_t)bm * 128 * DM, Bw, ldbg, bias,
        [&](wmma::fragment<wmma::accumulator, 16, 16, 8, float> (&acc)[4][4],
            int wm, int wn) {
            if (rnd) {
#pragma unroll
                for (int i = 0; i < 4; i++)
#pragma unroll
                    for (int j = 0; j < 4; j++)
                        for (int t = 0; t < acc[i][j].num_elements; t++)
                            acc[i][j].x[t] = TF32(acc[i][j].x[t]);
            }
            float* Cp = Cb + (size_t)(bm * 128 + wm * 64) * ldc + wn * 64;
#pragma unroll
            for (int i = 0; i < 4; i++)
#pragma unroll
                for (int j = 0; j < 4; j++)
                    wmma::store_matrix_sync(Cp + (size_t)(i * 16) * ldc + j * 16,
                                            acc[i][j], ldc, wmma::mem_row_major);
        });
}

// output projection: C = A @ Wo + bo (raw inputs, fragment rounding)
__global__ __launch_bounds__(128, 2) void gemm_out_kernel(
    const float* __restrict__ A, const float* __restrict__ Bw,
    const float* __restrict__ bias, float* __restrict__ C)
{
    int bn = blockIdx.x, bm = blockIdx.y;
    gemm_core(A + (size_t)bm * 128 * DM, Bw + bn * 128, DM, bias + bn * 128,
        [&](wmma::fragment<wmma::accumulator, 16, 16, 8, float> (&acc)[4][4],
            int wm, int wn) {
            float* Cp = C + (size_t)(bm * 128 + wm * 64) * DM + bn * 128 + wn * 64;
#pragma unroll
            for (int i = 0; i < 4; i++)
#pragma unroll
                for (int j = 0; j < 4; j++)
                    wmma::store_matrix_sync(Cp + (size_t)(i * 16) * DM + j * 16,
                                            acc[i][j], DM, wmma::mem_row_major);
        });
}

// ---------------------------------------------------------------------------
// rope3: Q rope in place; K rope -> Kp (tf32, head-permuted col'=(d%8)*8+d/8);
// V -> Vp (head-permuted copy). One launch.
// ---------------------------------------------------------------------------
#define ROPE_NQ (MTOT * NH * 32)
#define ROPE_NK (MTOT * NG * 32)
#define VPERM_N (MTOT * KVD)

__global__ void rope3_kernel(float* __restrict__ Qd,
                             const float* __restrict__ Kd, float* __restrict__ Kp,
                             const float* __restrict__ Vd, float* __restrict__ Vp)
{
    int idx = blockIdx.x * blockDim.x + threadIdx.x;
    if (idx < ROPE_NQ) {
        int i = idx & 31;
        int rest = idx >> 5;
        int t = (rest / NH) % TT;
        float freq = expf(-((2.0f * (float)i) / (float)DH) * 9.210340371976184f);
        float ang = (float)t * freq;
        float s, c;
        sincosf(ang, &s, &c);
        float* p = Qd + (size_t)rest * DH + 2 * i;
        float xe = p[0], xo = p[1];
        p[0] = xe * c - xo * s;
        p[1] = xe * s + xo * c;
        return;
    }
    idx -= ROPE_NQ;
    if (idx < ROPE_NK) {
        int i = idx & 31;
        int rest = idx >> 5;
        int t = (rest / NG) % TT;
        float freq = expf(-((2.0f * (float)i) / (float)DH) * 9.210340371976184f);
        float ang = (float)t * freq;
        float s, c;
        sincosf(ang, &s, &c);
        const float* p = Kd + (size_t)rest * DH + 2 * i;
        float xe = p[0], xo = p[1];
        float re = TF32(xe * c - xo * s);
        float ro = TF32(xe * s + xo * c);
        int d0 = 2 * i, d1 = 2 * i + 1;
        int c0 = ((d0 & 7) << 3) | (d0 >> 3);
        int c1 = ((d1 & 7) << 3) | (d1 >> 3);
        Kp[(size_t)rest * DH + c0] = re;
        Kp[(size_t)rest * DH + c1] = ro;
        return;
    }
    idx -= ROPE_NK;
    if (idx >= VPERM_N) return;
    int d = idx & 63;
    int hi = idx >> 6;
    int cc = ((d & 7) << 3) | (d >> 3);
    Vp[(size_t)hi * DH + cc] = Vd[idx];
}

// ---------------------------------------------------------------------------
// Register-resident causal attention, 32 q-rows per warp, j-pair S phase
// (4 independent mma chains). 4 warps x 32 rows = RQ 128. Grid 512, 2 CTAs/SM.
// ---------------------------------------------------------------------------
#define RQ   128
#define TK   64
#define KLDK 68
#define KLDV 72
#define ATT_SMEM ((2 * TK * KLDK + 2 * TK * KLDV) * 4)   // 71680 B

__global__ __launch_bounds__(128, 2) void attn_reg3_kernel(
    const float* __restrict__ Q, const float* __restrict__ K,
    const float* __restrict__ V, float* __restrict__ O)
{
    extern __shared__ float sm[];
    float* Kb = sm;
    float* Vb = sm + 2 * TK * KLDK;

    int tid = threadIdx.x, warp = tid >> 5, lane = tid & 31;
    int g = lane >> 2, tau = lane & 3;

    int idx = blockIdx.x;
    int qblk = 15 - (idx >> 5);
    int bh = idx & 31;
    int h = bh & 15, b = bh >> 4;
    int grp = h / HPG;
    int q0 = qblk * RQ;
    int ntiles = 2 * (qblk + 1);
    const float scale = 0.125f;

    const float* Kbase = K + (size_t)b * TT * KVD + grp * DH;
    const float* Vbase = V + (size_t)b * TT * KVD + grp * DH;

    auto issue = [&](int kt) {
        int buf = kt & 1, kb = kt * TK;
        float* kd = &Kb[buf * TK * KLDK];
        float* vd = &Vb[buf * TK * KLDV];
        for (int i = tid; i < 1024; i += 128) {
            int r = i >> 4, c = (i & 15) << 2;
            cp16(&kd[r * KLDK + c], Kbase + (size_t)(kb + r) * KVD + c);
            cp16(&vd[r * KLDV + c], Vbase + (size_t)(kb + r) * KVD + c);
        }
        cp_commit();
    };
    issue(0);
    issue(1);

    float qa[2][8][4];
#pragma unroll
    for (int m = 0; m < 2; m++) {
        const float* qp = Q + ((size_t)(b * TT + q0 + warp * 32 + m * 16)) * DM + h * DH;
#pragma unroll
        for (int kb = 0; kb < 8; kb++) {
            const float* qq = qp + kb * 8;
            qa[m][kb][0] = TF32(qq[(size_t)g * DM + tau] * scale);
            qa[m][kb][1] = TF32(qq[(size_t)(g + 8) * DM + tau] * scale);
            qa[m][kb][2] = TF32(qq[(size_t)g * DM + tau + 4] * scale);
            qa[m][kb][3] = TF32(qq[(size_t)(g + 8) * DM + tau + 4] * scale);
        }
    }

    float oc[2][8][4];
#pragma unroll
    for (int m = 0; m < 2; m++)
#pragma unroll
        for (int n = 0; n < 8; n++)
            oc[m][n][0] = oc[m][n][1] = oc[m][n][2] = oc[m][n][3] = 0.0f;
    float rsum[2][2];
    rsum[0][0] = rsum[0][1] = rsum[1][0] = rsum[1][1] = 0.0f;

    int base = lane & ~3;
    int src0 = base + (tau >> 1);
    int src1 = src0 + 2;
    bool odd = (tau & 1);

    for (int kt = 0; kt < ntiles; kt++) {
        if (kt + 1 < ntiles) cp_wait<1>(); else cp_wait<0>();
        __syncthreads();
        const float* Kt = &Kb[(kt & 1) * TK * KLDK];
        const float* Vt = &Vb[(kt & 1) * TK * KLDV];
        bool need_mask = (kt >= 2 * qblk);
        int kcol = kt * TK;

#pragma unroll
        for (int jp = 0; jp < 4; jp++) {
            // K b-frags for j0 = 2*jp, j1 = 2*jp+1 (vectorized, permuted layout)
            float bb[2][2][8];
#pragma unroll
            for (int jj = 0; jj < 2; jj++) {
                const float* krow = &Kt[((jp * 2 + jj) * 8 + g) * KLDK];
                float4 k0a = *(const float4*)(krow + tau * 8);
                float4 k0b = *(const float4*)(krow + tau * 8 + 4);
                float4 k1a = *(const float4*)(krow + (tau + 4) * 8);
                float4 k1b = *(const float4*)(krow + (tau + 4) * 8 + 4);
                bb[jj][0][0] = k0a.x; bb[jj][0][1] = k0a.y;
                bb[jj][0][2] = k0a.z; bb[jj][0][3] = k0a.w;
                bb[jj][0][4] = k0b.x; bb[jj][0][5] = k0b.y;
                bb[jj][0][6] = k0b.z; bb[jj][0][7] = k0b.w;
                bb[jj][1][0] = k1a.x; bb[jj][1][1] = k1a.y;
                bb[jj][1][2] = k1a.z; bb[jj][1][3] = k1a.w;
                bb[jj][1][4] = k1b.x; bb[jj][1][5] = k1b.y;
                bb[jj][1][6] = k1b.z; bb[jj][1][7] = k1b.w;
            }

            // S: 4 independent chains (2 j x 2 m)
            float sa[2][2][4];
#pragma unroll
            for (int jj = 0; jj < 2; jj++)
#pragma unroll
                for (int m = 0; m < 2; m++)
                    sa[jj][m][0] = sa[jj][m][1] = sa[jj][m][2] = sa[jj][m][3] = 0.0f;
#pragma unroll
            for (int kb = 0; kb < 8; kb++)
#pragma unroll
                for (int jj = 0; jj < 2; jj++)
#pragma unroll
                    for (int m = 0; m < 2; m++)
                        mma16n8k8(sa[jj][m][0], sa[jj][m][1], sa[jj][m][2], sa[jj][m][3],
                                  qa[m][kb][0], qa[m][kb][1], qa[m][kb][2], qa[m][kb][3],
                                  bb[jj][0][kb], bb[jj][1][kb]);

            // exp + shfl + PV per jj
#pragma unroll
            for (int jj = 0; jj < 2; jj++) {
                int j = jp * 2 + jj;
                float af[2][4];
#pragma unroll
                for (int m = 0; m < 2; m++) {
                    int row0 = q0 + warp * 32 + m * 16 + g;
                    int row1 = row0 + 8;
                    float p0, p1, p2, p3;
                    if (need_mask) {
                        int c = kcol + j * 8 + 2 * tau;
                        p0 = (c     <= row0) ? __expf(sa[jj][m][0]) : 0.0f;
                        p1 = (c + 1 <= row0) ? __expf(sa[jj][m][1]) : 0.0f;
                        p2 = (c     <= row1) ? __expf(sa[jj][m][2]) : 0.0f;
                        p3 = (c + 1 <= row1) ? __expf(sa[jj][m][3]) : 0.0f;
                    } else {
                        p0 = __expf(sa[jj][m][0]); p1 = __expf(sa[jj][m][1]);
                        p2 = __expf(sa[jj][m][2]); p3 = __expf(sa[jj][m][3]);
                    }
                    rsum[m][0] += p0 + p1;
                    rsum[m][1] += p2 + p3;
                    float w0 = __shfl_sync(0xffffffffu, p0, src0);
                    float w1 = __shfl_sync(0xffffffffu, p1, src0);
                    float a0 = odd ? w1 : w0;
                    float w2 = __shfl_sync(0xffffffffu, p0, src1);
                    float w3 = __shfl_sync(0xffffffffu, p1, src1);
                    float a2 = odd ? w3 : w2;
                    float w4 = __shfl_sync(0xffffffffu, p2, src0);
                    float w5 = __shfl_sync(0xffffffffu, p3, src0);
                    float a1 = odd ? w5 : w4;
                    float w6 = __shfl_sync(0xffffffffu, p2, src1);
                    float w7 = __shfl_sync(0xffffffffu, p3, src1);
                    float a3 = odd ? w7 : w6;
                    af[m][0] = TF32(a0); af[m][1] = TF32(a1);
                    af[m][2] = TF32(a2); af[m][3] = TF32(a3);
                }
                const float* vr0 = &Vt[(j * 8 + tau) * KLDV + g * 8];
                const float* vr1 = &Vt[(j * 8 + tau + 4) * KLDV + g * 8];
#pragma unroll
                for (int n = 0; n < 8; n++) {
                    float b0 = vr0[n];
                    float b1 = vr1[n];
#pragma unroll
                    for (int m = 0; m < 2; m++)
                        mma16n8k8(oc[m][n][0], oc[m][n][1], oc[m][n][2], oc[m][n][3],
                                  af[m][0], af[m][1], af[m][2], af[m][3], b0, b1);
                }
            }
        }
        __syncthreads();
        if (kt + 2 < ntiles) issue(kt + 2);
    }

    // quad-reduce row sums, normalize, store
#pragma unroll
    for (int m = 0; m < 2; m++) {
        float rs0 = rsum[m][0], rs1 = rsum[m][1];
        rs0 += __shfl_xor_sync(0xffffffffu, rs0, 1);
        rs0 += __shfl_xor_sync(0xffffffffu, rs0, 2);
        rs1 += __shfl_xor_sync(0xffffffffu, rs1, 1);
        rs1 += __shfl_xor_sync(0xffffffffu, rs1, 2);
        float inv0 = 1.0f / rs0, inv1 = 1.0f / rs1;
        int row0 = q0 + warp * 32 + m * 16 + g;
        float* o0 = O + ((size_t)(b * TT + row0)) * DM + h * DH + 2 * tau;
        float* o1 = O + ((size_t)(b * TT + row0 + 8)) * DM + h * DH + 2 * tau;
#pragma unroll
        for (int n = 0; n < 8; n++) {
            float2 v0, v1;
            v0.x = TF32(oc[m][n][0] * inv0); v0.y = TF32(oc[m][n][1] * inv0);
            v1.x = TF32(oc[m][n][2] * inv1); v1.y = TF32(oc[m][n][3] * inv1);
            *(float2*)(o0 + n * 8) = v0;
            *(float2*)(o1 + n * 8) = v1;
        }
    }
}

// ---------------------------------------------------------------------------
extern "C" void kernel_launch(void* const* d_in, const int* in_sizes, int n_in,
                              void* d_out, int out_size)
{
    const float* x  = (const float*)d_in[0];
    const float* Wq = (const float*)d_in[1];
    const float* bq = (const float*)d_in[2];
    const float* Wk = (const float*)d_in[3];
    const float* bk = (const float*)d_in[4];
    const float* Wv = (const float*)d_in[5];
    const float* bv = (const float*)d_in[6];
    const float* Wo = (const float*)d_in[7];
    const float* bo = (const float*)d_in[8];
    float* out = (float*)d_out;

    float *Q, *Kp, *Vp, *Kpp, *Vpp, *Ap;
    cudaGetSymbolAddress((void**)&Q,   g_Q);
    cudaGetSymbolAddress((void**)&Kp,  g_K);
    cudaGetSymbolAddress((void**)&Vp,  g_V);
    cudaGetSymbolAddress((void**)&Kpp, g_Kp);
    cudaGetSymbolAddress((void**)&Vpp, g_Vp);
    cudaGetSymbolAddress((void**)&Ap,  g_A);

    cudaFuncSetAttribute((const void*)gemm_qkv_kernel,
                         cudaFuncAttributeMaxDynamicSharedMemorySize, GSMEM);
    cudaFuncSetAttribute((const void*)gemm_out_kernel,
                         cudaFuncAttributeMaxDynamicSharedMemorySize, GSMEM);
    cudaFuncSetAttribute((const void*)attn_reg3_kernel,
                         cudaFuncAttributeMaxDynamicSharedMemorySize, ATT_SMEM);

    // fused QKV projection (reads raw inputs; rounds fragments in-register)
    dim3 gqkv(12, MTOT / 128);            // (12, 32)
    gemm_qkv_kernel<<<gqkv, 128, GSMEM>>>(x, Wq, Wk, Wv, bq, bk, bv, Q, Kp, Vp);

    // rope Q in place; rope+permute K -> Kp'; permute V -> Vp'
    int nr = ROPE_NQ + ROPE_NK + VPERM_N;
    rope3_kernel<<<(nr + 255) / 256, 256>>>(Q, Kp, Kpp, Vp, Vpp);

    // attention
    attn_reg3_kernel<<<512, 128, ATT_SMEM>>>(Q, Kpp, Vpp, Ap);

    // output projection
    dim3 go(DM / 128, MTOT / 128);        // (8, 32)
    gemm_out_kernel<<<go, 128, GSMEM>>>(Ap, Wo, bo, out);
}

// round 11
// speedup vs baseline: 1.0491x; 1.0491x over previous
#include <cuda_runtime.h>
#include <cstdint>
#include <math.h>
#include <mma.h>

using namespace nvcuda;

// Problem constants
#define BB   2
#define TT   2048
#define DM   1024
#define NH   16
#define NG   4
#define DH   64
#define HPG  (NH / NG)          // 4
#define MTOT (BB * TT)          // 4096
#define KVD  (NG * DH)          // 256
#define NQKV (DM + 2 * KVD)     // 1536

#define TF32(x) wmma::__float_to_tf32(x)

// Scratch (no cudaMalloc allowed)
static __device__ float g_Q[(size_t)MTOT * DM];
static __device__ float g_K[(size_t)MTOT * KVD];
static __device__ float g_V[(size_t)MTOT * KVD];
static __device__ float g_Kp[(size_t)MTOT * KVD];   // rope'd, tf32, head-permuted
static __device__ float g_Vp[(size_t)MTOT * KVD];   // tf32, head-permuted
static __device__ float g_A[(size_t)MTOT * DM];
static __device__ float g_X   [(size_t)MTOT * DM];
static __device__ float g_Wqkv[(size_t)DM * NQKV];
static __device__ float g_bqkv[NQKV];
static __device__ float g_Wo  [(size_t)DM * DM];

// ---------------------------------------------------------------------------
// helpers
// ---------------------------------------------------------------------------
__device__ __forceinline__ void cp16(void* s, const void* g) {
    unsigned int sa = (unsigned int)__cvta_generic_to_shared(s);
    asm volatile("cp.async.cg.shared.global [%0], [%1], 16;\n" :: "r"(sa), "l"(g));
}
__device__ __forceinline__ void cp_commit() { asm volatile("cp.async.commit_group;\n"); }
template<int N> __device__ __forceinline__ void cp_wait() {
    asm volatile("cp.async.wait_group %0;\n" :: "n"(N));
}

// mma.m16n8k8 tf32: D += A * B  (A row-major 16x8, B col-major 8x8)
__device__ __forceinline__ void mma16n8k8(
    float& d0, float& d1, float& d2, float& d3,
    float a0, float a1, float a2, float a3, float b0, float b1)
{
    unsigned int ua0 = __float_as_uint(a0), ua1 = __float_as_uint(a1);
    unsigned int ua2 = __float_as_uint(a2), ua3 = __float_as_uint(a3);
    unsigned int ub0 = __float_as_uint(b0), ub1 = __float_as_uint(b1);
    asm volatile(
        "mma.sync.aligned.m16n8k8.row.col.f32.tf32.tf32.f32 "
        "{%0,%1,%2,%3}, {%4,%5,%6,%7}, {%8,%9}, {%0,%1,%2,%3};"
        : "+f"(d0), "+f"(d1), "+f"(d2), "+f"(d3)
        : "r"(ua0), "r"(ua1), "r"(ua2), "r"(ua3), "r"(ub0), "r"(ub1));
}

// ---------------------------------------------------------------------------
// prepass: tf32-round mma operands; pack Wq|Wk|Wv -> Wqkv, bq|bk|bv -> bqkv.
// ---------------------------------------------------------------------------
#define N4_X   (MTOT * DM / 4)
#define N4_QO  (DM * DM / 4)
#define N4_KV  (DM * KVD / 4)
#define N4_B   (NQKV / 4)
#define N4_TOT (N4_X + N4_QO + 2 * N4_KV + N4_QO + N4_B)

__global__ void prep_kernel(
    const float* __restrict__ x,  const float* __restrict__ Wq,
    const float* __restrict__ Wk, const float* __restrict__ Wv,
    const float* __restrict__ Wo,
    const float* __restrict__ bq, const float* __restrict__ bk,
    const float* __restrict__ bv,
    float* __restrict__ Xr, float* __restrict__ wqkv,
    float* __restrict__ wo, float* __restrict__ bqkv)
{
    int i = blockIdx.x * blockDim.x + threadIdx.x;
    if (i >= N4_TOT) return;
    int off = i;
    if (off < N4_X) {
        float4 v = ((const float4*)x)[off];
        v.x = TF32(v.x); v.y = TF32(v.y); v.z = TF32(v.z); v.w = TF32(v.w);
        ((float4*)Xr)[off] = v;
        return;
    }
    off -= N4_X;
    if (off < N4_QO) {
        float4 v = ((const float4*)Wq)[off];
        v.x = TF32(v.x); v.y = TF32(v.y); v.z = TF32(v.z); v.w = TF32(v.w);
        int r = off >> 8, c = off & 255;
        ((float4*)wqkv)[r * (NQKV / 4) + c] = v;
        return;
    }
    off -= N4_QO;
    if (off < N4_KV) {
        float4 v = ((const float4*)Wk)[off];
        v.x = TF32(v.x); v.y = TF32(v.y); v.z = TF32(v.z); v.w = TF32(v.w);
        int r = off >> 6, c = off & 63;
        ((float4*)wqkv)[r * (NQKV / 4) + 256 + c] = v;
        return;
    }
    off -= N4_KV;
    if (off < N4_KV) {
        float4 v = ((const float4*)Wv)[off];
        v.x = TF32(v.x); v.y = TF32(v.y); v.z = TF32(v.z); v.w = TF32(v.w);
        int r = off >> 6, c = off & 63;
        ((float4*)wqkv)[r * (NQKV / 4) + 320 + c] = v;
        return;
    }
    off -= N4_KV;
    if (off < N4_QO) {
        float4 v = ((const float4*)Wo)[off];
        v.x = TF32(v.x); v.y = TF32(v.y); v.z = TF32(v.z); v.w = TF32(v.w);
        ((float4*)wo)[off] = v;
        return;
    }
    off -= N4_QO;
    float4 v;
    if (off < 256)      v = ((const float4*)bq)[off];
    else if (off < 320) v = ((const float4*)bk)[off - 256];
    else                v = ((const float4*)bv)[off - 320];
    ((float4*)bqkv)[off] = v;
}

// ---------------------------------------------------------------------------
// Shared GEMM core: 128x128 tile, 4 warps (2x2 of 64x64), 3-stage cp.async.
// A,B pre-rounded to tf32 (prep_kernel). No in-fragment rounding.
// ---------------------------------------------------------------------------
#define BK 16
#define LDA (BK + 4)
#define LDB (128 + 4)
#define GST 3
#define GSMEM ((GST * (128 * LDA + BK * LDB)) * 4)   // 56064 B

template<typename EPI>
__device__ __forceinline__ void gemm_core(
    const float* __restrict__ Ap, const float* __restrict__ Bp, int ldbg,
    const float* __restrict__ biasp, EPI epi)
{
    extern __shared__ float smem[];
    float* As = smem;
    float* Bs = smem + GST * 128 * LDA;

    int tid = threadIdx.x;
    int warp = tid >> 5;
    int wm = warp & 1;
    int wn = warp >> 1;

    wmma::fragment<wmma::accumulator, 16, 16, 8, float> acc[4][4];

    for (int i = tid; i < 16 * 128; i += 128) {
        int r = i >> 7, c = i & 127;
        Bs[r * LDB + c] = biasp[c];
    }
    __syncthreads();
#pragma unroll
    for (int i = 0; i < 4; i++)
#pragma unroll
        for (int j = 0; j < 4; j++)
            wmma::load_matrix_sync(acc[i][j], &Bs[wn * 64 + j * 16], LDB,
                                   wmma::mem_row_major);
    __syncthreads();

    const int NIT = DM / BK;

    auto issueG = [&](int it) {
        int s = it % GST, k0 = it * BK;
        float* as = &As[s * 128 * LDA];
        float* bs = &Bs[s * BK * LDB];
#pragma unroll
        for (int i = tid; i < 512; i += 128) {
            int r = i >> 2, c = (i & 3) << 2;
            cp16(&as[r * LDA + c], Ap + (size_t)r * DM + k0 + c);
        }
#pragma unroll
        for (int i = tid; i < 512; i += 128) {
            int r = i >> 5, c = (i & 31) << 2;
            cp16(&bs[r * LDB + c], Bp + (size_t)(k0 + r) * ldbg + c);
        }
        cp_commit();
    };

    issueG(0); issueG(1); issueG(2);

    for (int it = 0; it < NIT; it++) {
        if (it + 3 <= NIT) cp_wait<2>();
        else if (it + 2 <= NIT) cp_wait<1>();
        else cp_wait<0>();
        __syncthreads();
        int s = it % GST;
        const float* as = &As[s * 128 * LDA];
        const float* bs = &Bs[s * BK * LDB];
#pragma unroll
        for (int ks = 0; ks < BK; ks += 8) {
            wmma::fragment<wmma::matrix_a, 16, 16, 8, wmma::precision::tf32, wmma::row_major> af[4];
            wmma::fragment<wmma::matrix_b, 16, 16, 8, wmma::precision::tf32, wmma::row_major> bf[4];
#pragma unroll
            for (int i = 0; i < 4; i++)
                wmma::load_matrix_sync(af[i], &as[(wm * 64 + i * 16) * LDA + ks], LDA);
#pragma unroll
            for (int j = 0; j < 4; j++)
                wmma::load_matrix_sync(bf[j], &bs[ks * LDB + wn * 64 + j * 16], LDB);
#pragma unroll
            for (int i = 0; i < 4; i++)
#pragma unroll
                for (int j = 0; j < 4; j++)
                    wmma::mma_sync(acc[i][j], af[i], bf[j], acc[i][j]);
        }
        __syncthreads();
        if (it + GST < NIT) issueG(it + GST);
    }

    epi(acc, wm, wn);
}

// fused QKV GEMM: bn 0..7 -> Q, 8..9 -> K, 10..11 -> V (tf32-rounded)
__global__ __launch_bounds__(128, 2) void gemm_qkv_kernel(
    const float* __restrict__ A, const float* __restrict__ Bw,
    const float* __restrict__ bias,
    float* __restrict__ Qo, float* __restrict__ Ko, float* __restrict__ Vo)
{
    int bn = blockIdx.x, bm = blockIdx.y;
    float* Cb; int ldc; bool rnd = false;
    if (bn < 8)       { Cb = Qo + bn * 128;          ldc = DM;  }
    else if (bn < 10) { Cb = Ko + (bn - 8) * 128;    ldc = KVD; }
    else              { Cb = Vo + (bn - 10) * 128;   ldc = KVD; rnd = true; }

    gemm_core(A + (size_t)bm * 128 * DM, Bw + bn * 128, NQKV, bias + bn * 128,
        [&](wmma::fragment<wmma::accumulator, 16, 16, 8, float> (&acc)[4][4],
            int wm, int wn) {
            if (rnd) {
#pragma unroll
                for (int i = 0; i < 4; i++)
#pragma unroll
                    for (int j = 0; j < 4; j++)
                        for (int t = 0; t < acc[i][j].num_elements; t++)
                            acc[i][j].x[t] = TF32(acc[i][j].x[t]);
            }
            float* Cp = Cb + (size_t)(bm * 128 + wm * 64) * ldc + wn * 64;
#pragma unroll
            for (int i = 0; i < 4; i++)
#pragma unroll
                for (int j = 0; j < 4; j++)
                    wmma::store_matrix_sync(Cp + (size_t)(i * 16) * ldc + j * 16,
                                            acc[i][j], ldc, wmma::mem_row_major);
        });
}

// plain GEMM (output projection)
__global__ __launch_bounds__(128, 2) void gemm_out_kernel(
    const float* __restrict__ A, const float* __restrict__ Bw,
    const float* __restrict__ bias, float* __restrict__ C)
{
    int bn = blockIdx.x, bm = blockIdx.y;
    gemm_core(A + (size_t)bm * 128 * DM, Bw + bn * 128, DM, bias + bn * 128,
        [&](wmma::fragment<wmma::accumulator, 16, 16, 8, float> (&acc)[4][4],
            int wm, int wn) {
            float* Cp = C + (size_t)(bm * 128 + wm * 64) * DM + bn * 128 + wn * 64;
#pragma unroll
            for (int i = 0; i < 4; i++)
#pragma unroll
                for (int j = 0; j < 4; j++)
                    wmma::store_matrix_sync(Cp + (size_t)(i * 16) * DM + j * 16,
                                            acc[i][j], DM, wmma::mem_row_major);
        });
}

// ---------------------------------------------------------------------------
// rope3: Q rope in place; K rope -> Kp (tf32, head-permuted col'=(d%8)*8+d/8);
// V -> Vp (head-permuted copy). One launch.
// ---------------------------------------------------------------------------
#define ROPE_NQ (MTOT * NH * 32)
#define ROPE_NK (MTOT * NG * 32)
#define VPERM_N (MTOT * KVD)

__global__ void rope3_kernel(float* __restrict__ Qd,
                             const float* __restrict__ Kd, float* __restrict__ Kp,
                             const float* __restrict__ Vd, float* __restrict__ Vp)
{
    int idx = blockIdx.x * blockDim.x + threadIdx.x;
    if (idx < ROPE_NQ) {
        int i = idx & 31;
        int rest = idx >> 5;
        int t = (rest / NH) % TT;
        float freq = expf(-((2.0f * (float)i) / (float)DH) * 9.210340371976184f);
        float ang = (float)t * freq;
        float s, c;
        sincosf(ang, &s, &c);
        float* p = Qd + (size_t)rest * DH + 2 * i;
        float xe = p[0], xo = p[1];
        p[0] = xe * c - xo * s;
        p[1] = xe * s + xo * c;
        return;
    }
    idx -= ROPE_NQ;
    if (idx < ROPE_NK) {
        int i = idx & 31;
        int rest = idx >> 5;
        int t = (rest / NG) % TT;
        float freq = expf(-((2.0f * (float)i) / (float)DH) * 9.210340371976184f);
        float ang = (float)t * freq;
        float s, c;
        sincosf(ang, &s, &c);
        const float* p = Kd + (size_t)rest * DH + 2 * i;
        float xe = p[0], xo = p[1];
        float re = TF32(xe * c - xo * s);
        float ro = TF32(xe * s + xo * c);
        int d0 = 2 * i, d1 = 2 * i + 1;
        int c0 = ((d0 & 7) << 3) | (d0 >> 3);
        int c1 = ((d1 & 7) << 3) | (d1 >> 3);
        Kp[(size_t)rest * DH + c0] = re;
        Kp[(size_t)rest * DH + c1] = ro;
        return;
    }
    idx -= ROPE_NK;
    if (idx >= VPERM_N) return;
    int d = idx & 63;
    int hi = idx >> 6;
    int cc = ((d & 7) << 3) | (d >> 3);
    Vp[(size_t)hi * DH + cc] = Vd[idx];
}

// ---------------------------------------------------------------------------
// Register-resident causal attention, 32 q-rows per warp, j-pair S phase
// (4 independent mma chains). 4 warps x 32 rows = RQ 128. Grid 512, 2 CTAs/SM.
// ---------------------------------------------------------------------------
#define RQ   128
#define TK   64
#define KLDK 68
#define KLDV 72
#define ATT_SMEM ((2 * TK * KLDK + 2 * TK * KLDV) * 4)   // 71680 B

__global__ __launch_bounds__(128, 2) void attn_reg3_kernel(
    const float* __restrict__ Q, const float* __restrict__ K,
    const float* __restrict__ V, float* __restrict__ O)
{
    extern __shared__ float sm[];
    float* Kb = sm;
    float* Vb = sm + 2 * TK * KLDK;

    int tid = threadIdx.x, warp = tid >> 5, lane = tid & 31;
    int g = lane >> 2, tau = lane & 3;

    int idx = blockIdx.x;
    int qblk = 15 - (idx >> 5);
    int bh = idx & 31;
    int h = bh & 15, b = bh >> 4;
    int grp = h / HPG;
    int q0 = qblk * RQ;
    int ntiles = 2 * (qblk + 1);
    const float scale = 0.125f;

    const float* Kbase = K + (size_t)b * TT * KVD + grp * DH;
    const float* Vbase = V + (size_t)b * TT * KVD + grp * DH;

    auto issue = [&](int kt) {
        int buf = kt & 1, kb = kt * TK;
        float* kd = &Kb[buf * TK * KLDK];
        float* vd = &Vb[buf * TK * KLDV];
        for (int i = tid; i < 1024; i += 128) {
            int r = i >> 4, c = (i & 15) << 2;
            cp16(&kd[r * KLDK + c], Kbase + (size_t)(kb + r) * KVD + c);
            cp16(&vd[r * KLDV + c], Vbase + (size_t)(kb + r) * KVD + c);
        }
        cp_commit();
    };
    issue(0);
    issue(1);

    float qa[2][8][4];
#pragma unroll
    for (int m = 0; m < 2; m++) {
        const float* qp = Q + ((size_t)(b * TT + q0 + warp * 32 + m * 16)) * DM + h * DH;
#pragma unroll
        for (int kb = 0; kb < 8; kb++) {
            const float* qq = qp + kb * 8;
            qa[m][kb][0] = TF32(qq[(size_t)g * DM + tau] * scale);
            qa[m][kb][1] = TF32(qq[(size_t)(g + 8) * DM + tau] * scale);
            qa[m][kb][2] = TF32(qq[(size_t)g * DM + tau + 4] * scale);
            qa[m][kb][3] = TF32(qq[(size_t)(g + 8) * DM + tau + 4] * scale);
        }
    }

    float oc[2][8][4];
#pragma unroll
    for (int m = 0; m < 2; m++)
#pragma unroll
        for (int n = 0; n < 8; n++)
            oc[m][n][0] = oc[m][n][1] = oc[m][n][2] = oc[m][n][3] = 0.0f;
    float rsum[2][2];
    rsum[0][0] = rsum[0][1] = rsum[1][0] = rsum[1][1] = 0.0f;

    int base = lane & ~3;
    int src0 = base + (tau >> 1);
    int src1 = src0 + 2;
    bool odd = (tau & 1);

    for (int kt = 0; kt < ntiles; kt++) {
        if (kt + 1 < ntiles) cp_wait<1>(); else cp_wait<0>();
        __syncthreads();
        const float* Kt = &Kb[(kt & 1) * TK * KLDK];
        const float* Vt = &Vb[(kt & 1) * TK * KLDV];
        bool need_mask = (kt >= 2 * qblk);
        int kcol = kt * TK;

#pragma unroll
        for (int jp = 0; jp < 4; jp++) {
            float bb[2][2][8];
#pragma unroll
            for (int jj = 0; jj < 2; jj++) {
                const float* krow = &Kt[((jp * 2 + jj) * 8 + g) * KLDK];
                float4 k0a = *(const float4*)(krow + tau * 8);
                float4 k0b = *(const float4*)(krow + tau * 8 + 4);
                float4 k1a = *(const float4*)(krow + (tau + 4) * 8);
                float4 k1b = *(const float4*)(krow + (tau + 4) * 8 + 4);
                bb[jj][0][0] = k0a.x; bb[jj][0][1] = k0a.y;
                bb[jj][0][2] = k0a.z; bb[jj][0][3] = k0a.w;
                bb[jj][0][4] = k0b.x; bb[jj][0][5] = k0b.y;
                bb[jj][0][6] = k0b.z; bb[jj][0][7] = k0b.w;
                bb[jj][1][0] = k1a.x; bb[jj][1][1] = k1a.y;
                bb[jj][1][2] = k1a.z; bb[jj][1][3] = k1a.w;
                bb[jj][1][4] = k1b.x; bb[jj][1][5] = k1b.y;
                bb[jj][1][6] = k1b.z; bb[jj][1][7] = k1b.w;
            }

            float sa[2][2][4];
#pragma unroll
            for (int jj = 0; jj < 2; jj++)
#pragma unroll
                for (int m = 0; m < 2; m++)
                    sa[jj][m][0] = sa[jj][m][1] = sa[jj][m][2] = sa[jj][m][3] = 0.0f;
#pragma unroll
            for (int kb = 0; kb < 8; kb++)
#pragma unroll
                for (int jj = 0; jj < 2; jj++)
#pragma unroll
                    for (int m = 0; m < 2; m++)
                        mma16n8k8(sa[jj][m][0], sa[jj][m][1], sa[jj][m][2], sa[jj][m][3],
                                  qa[m][kb][0], qa[m][kb][1], qa[m][kb][2], qa[m][kb][3],
                                  bb[jj][0][kb], bb[jj][1][kb]);

#pragma unroll
            for (int jj = 0; jj < 2; jj++) {
                int j = jp * 2 + jj;
                float af[2][4];
#pragma unroll
                for (int m = 0; m < 2; m++) {
                    int row0 = q0 + warp * 32 + m * 16 + g;
                    int row1 = row0 + 8;
                    float p0, p1, p2, p3;
                    if (need_mask) {
                        int c = kcol + j * 8 + 2 * tau;
                        p0 = (c     <= row0) ? __expf(sa[jj][m][0]) : 0.0f;
                        p1 = (c + 1 <= row0) ? __expf(sa[jj][m][1]) : 0.0f;
                        p2 = (c     <= row1) ? __expf(sa[jj][m][2]) : 0.0f;
                        p3 = (c + 1 <= row1) ? __expf(sa[jj][m][3]) : 0.0f;
                    } else {
                        p0 = __expf(sa[jj][m][0]); p1 = __expf(sa[jj][m][1]);
                        p2 = __expf(sa[jj][m][2]); p3 = __expf(sa[jj][m][3]);
                    }
                    rsum[m][0] += p0 + p1;
                    rsum[m][1] += p2 + p3;
                    float w0 = __shfl_sync(0xffffffffu, p0, src0);
                    float w1 = __shfl_sync(0xffffffffu, p1, src0);
                    float a0 = odd ? w1 : w0;
                    float w2 = __shfl_sync(0xffffffffu, p0, src1);
                    float w3 = __shfl_sync(0xffffffffu, p1, src1);
                    float a2 = odd ? w3 : w2;
                    float w4 = __shfl_sync(0xffffffffu, p2, src0);
                    float w5 = __shfl_sync(0xffffffffu, p3, src0);
                    float a1 = odd ? w5 : w4;
                    float w6 = __shfl_sync(0xffffffffu, p2, src1);
                    float w7 = __shfl_sync(0xffffffffu, p3, src1);
                    float a3 = odd ? w7 : w6;
                    af[m][0] = TF32(a0); af[m][1] = TF32(a1);
                    af[m][2] = TF32(a2); af[m][3] = TF32(a3);
                }
                const float* vr0 = &Vt[(j * 8 + tau) * KLDV + g * 8];
                const float* vr1 = &Vt[(j * 8 + tau + 4) * KLDV + g * 8];
#pragma unroll
                for (int n = 0; n < 8; n++) {
                    float b0 = vr0[n];
                    float b1 = vr1[n];
#pragma unroll
                    for (int m = 0; m < 2; m++)
                        mma16n8k8(oc[m][n][0], oc[m][n][1], oc[m][n][2], oc[m][n][3],
                                  af[m][0], af[m][1], af[m][2], af[m][3], b0, b1);
                }
            }
        }
        __syncthreads();
        if (kt + 2 < ntiles) issue(kt + 2);
    }

#pragma unroll
    for (int m = 0; m < 2; m++) {
        float rs0 = rsum[m][0], rs1 = rsum[m][1];
        rs0 += __shfl_xor_sync(0xffffffffu, rs0, 1);
        rs0 += __shfl_xor_sync(0xffffffffu, rs0, 2);
        rs1 += __shfl_xor_sync(0xffffffffu, rs1, 1);
        rs1 += __shfl_xor_sync(0xffffffffu, rs1, 2);
        float inv0 = 1.0f / rs0, inv1 = 1.0f / rs1;
        int row0 = q0 + warp * 32 + m * 16 + g;
        float* o0 = O + ((size_t)(b * TT + row0)) * DM + h * DH + 2 * tau;
        float* o1 = O + ((size_t)(b * TT + row0 + 8)) * DM + h * DH + 2 * tau;
#pragma unroll
        for (int n = 0; n < 8; n++) {
            float2 v0, v1;
            v0.x = TF32(oc[m][n][0] * inv0); v0.y = TF32(oc[m][n][1] * inv0);
            v1.x = TF32(oc[m][n][2] * inv1); v1.y = TF32(oc[m][n][3] * inv1);
            *(float2*)(o0 + n * 8) = v0;
            *(float2*)(o1 + n * 8) = v1;
        }
    }
}

// ---------------------------------------------------------------------------
extern "C" void kernel_launch(void* const* d_in, const int* in_sizes, int n_in,
                              void* d_out, int out_size)
{
    const float* x  = (const float*)d_in[0];
    const float* Wq = (const float*)d_in[1];
    const float* bq = (const float*)d_in[2];
    const float* Wk = (const float*)d_in[3];
    const float* bk = (const float*)d_in[4];
    const float* Wv = (const float*)d_in[5];
    const float* bv = (const float*)d_in[6];
    const float* Wo = (const float*)d_in[7];
    const float* bo = (const float*)d_in[8];
    float* out = (float*)d_out;

    float *Q, *Kp, *Vp, *Kpp, *Vpp, *Ap, *Xr, *wqkv, *bqkv, *wo;
    cudaGetSymbolAddress((void**)&Q,    g_Q);
    cudaGetSymbolAddress((void**)&Kp,   g_K);
    cudaGetSymbolAddress((void**)&Vp,   g_V);
    cudaGetSymbolAddress((void**)&Kpp,  g_Kp);
    cudaGetSymbolAddress((void**)&Vpp,  g_Vp);
    cudaGetSymbolAddress((void**)&Ap,   g_A);
    cudaGetSymbolAddress((void**)&Xr,   g_X);
    cudaGetSymbolAddress((void**)&wqkv, g_Wqkv);
    cudaGetSymbolAddress((void**)&bqkv, g_bqkv);
    cudaGetSymbolAddress((void**)&wo,   g_Wo);

    cudaFuncSetAttribute((const void*)gemm_qkv_kernel,
                         cudaFuncAttributeMaxDynamicSharedMemorySize, GSMEM);
    cudaFuncSetAttribute((const void*)gemm_out_kernel,
                         cudaFuncAttributeMaxDynamicSharedMemorySize, GSMEM);
    cudaFuncSetAttribute((const void*)attn_reg3_kernel,
                         cudaFuncAttributeMaxDynamicSharedMemorySize, ATT_SMEM);

    // prepass: round + pack
    prep_kernel<<<(N4_TOT + 255) / 256, 256>>>(x, Wq, Wk, Wv, Wo, bq, bk, bv,
                                               Xr, wqkv, wo, bqkv);

    // fused QKV projection
    dim3 gqkv(NQKV / 128, MTOT / 128);    // (12, 32)
    gemm_qkv_kernel<<<gqkv, 128, GSMEM>>>(Xr, wqkv, bqkv, Q, Kp, Vp);

    // rope Q in place; rope+permute K -> Kp'; permute V -> Vp'
    int nr = ROPE_NQ + ROPE_NK + VPERM_N;
    rope3_kernel<<<(nr + 255) / 256, 256>>>(Q, Kp, Kpp, Vp, Vpp);

    // attention
    attn_reg3_kernel<<<512, 128, ATT_SMEM>>>(Q, Kpp, Vpp, Ap);

    // output projection
    dim3 go(DM / 128, MTOT / 128);        // (8, 32)
    gemm_out_kernel<<<go, 128, GSMEM>>>(Ap, wo, bo, out);
}

// round 13
// speedup vs baseline: 1.1843x; 1.1289x over previous
#include <cuda_runtime.h>
#include <cuda_fp16.h>
#include <cstdint>
#include <math.h>
#include <mma.h>

using namespace nvcuda;

// Problem constants
#define BB   2
#define TT   2048
#define DM   1024
#define NH   16
#define NG   4
#define DH   64
#define HPG  (NH / NG)          // 4
#define MTOT (BB * TT)          // 4096
#define KVD  (NG * DH)          // 256
#define NQKV (DM + 2 * KVD)     // 1536

#define TF32(x) wmma::__float_to_tf32(x)

// Scratch (no cudaMalloc allowed)
static __device__ float  g_Q[(size_t)MTOT * DM];
static __device__ float  g_K[(size_t)MTOT * KVD];
static __device__ float  g_V[(size_t)MTOT * KVD];
static __device__ __half g_KpH[(size_t)MTOT * KVD];   // rope'd fp16 [b][t][grp][d]
static __device__ __half g_VpH[(size_t)MTOT * KVD];   // fp16 transposed [b][grp][d][t]
static __device__ float  g_A[(size_t)MTOT * DM];
static __device__ float  g_X   [(size_t)MTOT * DM];
static __device__ float  g_Wqkv[(size_t)DM * NQKV];
static __device__ float  g_bqkv[NQKV];
static __device__ float  g_Wo  [(size_t)DM * DM];

// ---------------------------------------------------------------------------
// helpers
// ---------------------------------------------------------------------------
__device__ __forceinline__ void cp16(void* s, const void* g) {
    unsigned int sa = (unsigned int)__cvta_generic_to_shared(s);
    asm volatile("cp.async.cg.shared.global [%0], [%1], 16;\n" :: "r"(sa), "l"(g));
}
__device__ __forceinline__ void cp_commit() { asm volatile("cp.async.commit_group;\n"); }
template<int N> __device__ __forceinline__ void cp_wait() {
    asm volatile("cp.async.wait_group %0;\n" :: "n"(N));
}

__device__ __forceinline__ unsigned int pack_h2(float a, float b) {
    __half2 h = __floats2half2_rn(a, b);
    return *(unsigned int*)&h;
}

// mma.m16n8k16 f16: D(f32) += A(f16) * B(f16); A row-major, B col-major
__device__ __forceinline__ void mma_f16(
    float& d0, float& d1, float& d2, float& d3,
    unsigned int a0, unsigned int a1, unsigned int a2, unsigned int a3,
    unsigned int b0, unsigned int b1)
{
    asm volatile(
        "mma.sync.aligned.m16n8k16.row.col.f32.f16.f16.f32 "
        "{%0,%1,%2,%3}, {%4,%5,%6,%7}, {%8,%9}, {%0,%1,%2,%3};"
        : "+f"(d0), "+f"(d1), "+f"(d2), "+f"(d3)
        : "r"(a0), "r"(a1), "r"(a2), "r"(a3), "r"(b0), "r"(b1));
}

// ---------------------------------------------------------------------------
// prepass: tf32-round GEMM operands; pack Wq|Wk|Wv -> Wqkv, bq|bk|bv -> bqkv.
// ---------------------------------------------------------------------------
#define N4_X   (MTOT * DM / 4)
#define N4_QO  (DM * DM / 4)
#define N4_KV  (DM * KVD / 4)
#define N4_B   (NQKV / 4)
#define N4_TOT (N4_X + N4_QO + 2 * N4_KV + N4_QO + N4_B)

__global__ void prep_kernel(
    const float* __restrict__ x,  const float* __restrict__ Wq,
    const float* __restrict__ Wk, const float* __restrict__ Wv,
    const float* __restrict__ Wo,
    const float* __restrict__ bq, const float* __restrict__ bk,
    const float* __restrict__ bv,
    float* __restrict__ Xr, float* __restrict__ wqkv,
    float* __restrict__ wo, float* __restrict__ bqkv)
{
    int i = blockIdx.x * blockDim.x + threadIdx.x;
    if (i >= N4_TOT) return;
    int off = i;
    if (off < N4_X) {
        float4 v = ((const float4*)x)[off];
        v.x = TF32(v.x); v.y = TF32(v.y); v.z = TF32(v.z); v.w = TF32(v.w);
        ((float4*)Xr)[off] = v;
        return;
    }
    off -= N4_X;
    if (off < N4_QO) {
        float4 v = ((const float4*)Wq)[off];
        v.x = TF32(v.x); v.y = TF32(v.y); v.z = TF32(v.z); v.w = TF32(v.w);
        int r = off >> 8, c = off & 255;
        ((float4*)wqkv)[r * (NQKV / 4) + c] = v;
        return;
    }
    off -= N4_QO;
    if (off < N4_KV) {
        float4 v = ((const float4*)Wk)[off];
        v.x = TF32(v.x); v.y = TF32(v.y); v.z = TF32(v.z); v.w = TF32(v.w);
        int r = off >> 6, c = off & 63;
        ((float4*)wqkv)[r * (NQKV / 4) + 256 + c] = v;
        return;
    }
    off -= N4_KV;
    if (off < N4_KV) {
        float4 v = ((const float4*)Wv)[off];
        v.x = TF32(v.x); v.y = TF32(v.y); v.z = TF32(v.z); v.w = TF32(v.w);
        int r = off >> 6, c = off & 63;
        ((float4*)wqkv)[r * (NQKV / 4) + 320 + c] = v;
        return;
    }
    off -= N4_KV;
    if (off < N4_QO) {
        float4 v = ((const float4*)Wo)[off];
        v.x = TF32(v.x); v.y = TF32(v.y); v.z = TF32(v.z); v.w = TF32(v.w);
        ((float4*)wo)[off] = v;
        return;
    }
    off -= N4_QO;
    float4 v;
    if (off < 256)      v = ((const float4*)bq)[off];
    else if (off < 320) v = ((const float4*)bk)[off - 256];
    else                v = ((const float4*)bv)[off - 320];
    ((float4*)bqkv)[off] = v;
}

// ---------------------------------------------------------------------------
// Shared GEMM core (unchanged from best-known): 128x128 tile, 4 warps,
// 3-stage cp.async. A,B pre-rounded to tf32.
// ---------------------------------------------------------------------------
#define BK 16
#define LDA (BK + 4)
#define LDB (128 + 4)
#define GST 3
#define GSMEM ((GST * (128 * LDA + BK * LDB)) * 4)   // 56064 B

template<typename EPI>
__device__ __forceinline__ void gemm_core(
    const float* __restrict__ Ap, const float* __restrict__ Bp, int ldbg,
    const float* __restrict__ biasp, EPI epi)
{
    extern __shared__ float smem[];
    float* As = smem;
    float* Bs = smem + GST * 128 * LDA;

    int tid = threadIdx.x;
    int warp = tid >> 5;
    int wm = warp & 1;
    int wn = warp >> 1;

    wmma::fragment<wmma::accumulator, 16, 16, 8, float> acc[4][4];

    for (int i = tid; i < 16 * 128; i += 128) {
        int r = i >> 7, c = i & 127;
        Bs[r * LDB + c] = biasp[c];
    }
    __syncthreads();
#pragma unroll
    for (int i = 0; i < 4; i++)
#pragma unroll
        for (int j = 0; j < 4; j++)
            wmma::load_matrix_sync(acc[i][j], &Bs[wn * 64 + j * 16], LDB,
                                   wmma::mem_row_major);
    __syncthreads();

    const int NIT = DM / BK;

    auto issueG = [&](int it) {
        int s = it % GST, k0 = it * BK;
        float* as = &As[s * 128 * LDA];
        float* bs = &Bs[s * BK * LDB];
#pragma unroll
        for (int i = tid; i < 512; i += 128) {
            int r = i >> 2, c = (i & 3) << 2;
            cp16(&as[r * LDA + c], Ap + (size_t)r * DM + k0 + c);
        }
#pragma unroll
        for (int i = tid; i < 512; i += 128) {
            int r = i >> 5, c = (i & 31) << 2;
            cp16(&bs[r * LDB + c], Bp + (size_t)(k0 + r) * ldbg + c);
        }
        cp_commit();
    };

    issueG(0); issueG(1); issueG(2);

    for (int it = 0; it < NIT; it++) {
        if (it + 3 <= NIT) cp_wait<2>();
        else if (it + 2 <= NIT) cp_wait<1>();
        else cp_wait<0>();
        __syncthreads();
        int s = it % GST;
        const float* as = &As[s * 128 * LDA];
        const float* bs = &Bs[s * BK * LDB];
#pragma unroll
        for (int ks = 0; ks < BK; ks += 8) {
            wmma::fragment<wmma::matrix_a, 16, 16, 8, wmma::precision::tf32, wmma::row_major> af[4];
            wmma::fragment<wmma::matrix_b, 16, 16, 8, wmma::precision::tf32, wmma::row_major> bf[4];
#pragma unroll
            for (int i = 0; i < 4; i++)
                wmma::load_matrix_sync(af[i], &as[(wm * 64 + i * 16) * LDA + ks], LDA);
#pragma unroll
            for (int j = 0; j < 4; j++)
                wmma::load_matrix_sync(bf[j], &bs[ks * LDB + wn * 64 + j * 16], LDB);
#pragma unroll
            for (int i = 0; i < 4; i++)
#pragma unroll
                for (int j = 0; j < 4; j++)
                    wmma::mma_sync(acc[i][j], af[i], bf[j], acc[i][j]);
        }
        __syncthreads();
        if (it + GST < NIT) issueG(it + GST);
    }

    epi(acc, wm, wn);
}

// fused QKV GEMM: bn 0..7 -> Q, 8..9 -> K, 10..11 -> V
__global__ __launch_bounds__(128, 2) void gemm_qkv_kernel(
    const float* __restrict__ A, const float* __restrict__ Bw,
    const float* __restrict__ bias,
    float* __restrict__ Qo, float* __restrict__ Ko, float* __restrict__ Vo)
{
    int bn = blockIdx.x, bm = blockIdx.y;
    float* Cb; int ldc;
    if (bn < 8)       { Cb = Qo + bn * 128;          ldc = DM;  }
    else if (bn < 10) { Cb = Ko + (bn - 8) * 128;    ldc = KVD; }
    else              { Cb = Vo + (bn - 10) * 128;   ldc = KVD; }

    gemm_core(A + (size_t)bm * 128 * DM, Bw + bn * 128, NQKV, bias + bn * 128,
        [&](wmma::fragment<wmma::accumulator, 16, 16, 8, float> (&acc)[4][4],
            int wm, int wn) {
            float* Cp = Cb + (size_t)(bm * 128 + wm * 64) * ldc + wn * 64;
#pragma unroll
            for (int i = 0; i < 4; i++)
#pragma unroll
                for (int j = 0; j < 4; j++)
                    wmma::store_matrix_sync(Cp + (size_t)(i * 16) * ldc + j * 16,
                                            acc[i][j], ldc, wmma::mem_row_major);
        });
}

// plain GEMM (output projection)
__global__ __launch_bounds__(128, 2) void gemm_out_kernel(
    const float* __restrict__ A, const float* __restrict__ Bw,
    const float* __restrict__ bias, float* __restrict__ C)
{
    int bn = blockIdx.x, bm = blockIdx.y;
    gemm_core(A + (size_t)bm * 128 * DM, Bw + bn * 128, DM, bias + bn * 128,
        [&](wmma::fragment<wmma::accumulator, 16, 16, 8, float> (&acc)[4][4],
            int wm, int wn) {
            float* Cp = C + (size_t)(bm * 128 + wm * 64) * DM + bn * 128 + wn * 64;
#pragma unroll
            for (int i = 0; i < 4; i++)
#pragma unroll
                for (int j = 0; j < 4; j++)
                    wmma::store_matrix_sync(Cp + (size_t)(i * 16) * DM + j * 16,
                                            acc[i][j], DM, wmma::mem_row_major);
        });
}

// ---------------------------------------------------------------------------
// rope3: Q rope in place (fp32); K rope -> KpH (fp16, [b][t][grp][d]);
// V -> VpH (fp16, transposed [b][grp][d][t]). One launch.
// ---------------------------------------------------------------------------
#define ROPE_NQ (MTOT * NH * 32)
#define ROPE_NK (MTOT * NG * 32)
#define VPERM_N (MTOT * KVD)

__global__ void rope3_kernel(float* __restrict__ Qd,
                             const float* __restrict__ Kd, __half* __restrict__ Kp,
                             const float* __restrict__ Vd, __half* __restrict__ Vp)
{
    int idx = blockIdx.x * blockDim.x + threadIdx.x;
    if (idx < ROPE_NQ) {
        int i = idx & 31;
        int rest = idx >> 5;
        int t = (rest / NH) % TT;
        float freq = expf(-((2.0f * (float)i) / (float)DH) * 9.210340371976184f);
        float ang = (float)t * freq;
        float s, c;
        sincosf(ang, &s, &c);
        float* p = Qd + (size_t)rest * DH + 2 * i;
        float xe = p[0], xo = p[1];
        p[0] = xe * c - xo * s;
        p[1] = xe * s + xo * c;
        return;
    }
    idx -= ROPE_NQ;
    if (idx < ROPE_NK) {
        int i = idx & 31;
        int rest = idx >> 5;
        int t = (rest / NG) % TT;
        float freq = expf(-((2.0f * (float)i) / (float)DH) * 9.210340371976184f);
        float ang = (float)t * freq;
        float s, c;
        sincosf(ang, &s, &c);
        const float* p = Kd + (size_t)rest * DH + 2 * i;
        float xe = p[0], xo = p[1];
        Kp[(size_t)rest * DH + 2 * i]     = __float2half(xe * c - xo * s);
        Kp[(size_t)rest * DH + 2 * i + 1] = __float2half(xe * s + xo * c);
        return;
    }
    idx -= ROPE_NK;
    if (idx >= VPERM_N) return;
    // idx ordered [b][grp][d][t] for coalesced writes
    int t = idx & (TT - 1);
    int rest2 = idx >> 11;          // b*NG*DH + grp*DH + d
    int d = rest2 & (DH - 1);
    int bg = rest2 >> 6;            // b*NG + grp
    int b = bg >> 2, grp = bg & 3;
    float v = Vd[((size_t)(b * TT + t)) * KVD + grp * DH + d];
    Vp[idx] = __float2half(v);
}

// ---------------------------------------------------------------------------
// FP16 register-resident causal attention (FA2 zero-shuffle P conversion).
// 4 warps x 32 q-rows = RQ 128. Grid 512 heavy-first, 2 CTAs/SM.
// K smem [key][dh] halves (pad 72); V smem [dh][key] halves (pad 72).
// ---------------------------------------------------------------------------
#define RQ   128
#define TK   64
#define KLDH 72
#define ATT_SMEM (2 * 2 * TK * KLDH * 2)   // 2 bufs x (K+V) x 64 x 72 halves = 36864 B

__global__ __launch_bounds__(128, 2) void attn_f16_kernel(
    const float* __restrict__ Q, const __half* __restrict__ K,
    const __half* __restrict__ V, float* __restrict__ O)
{
    extern __shared__ __half smh[];
    __half* Kb = smh;                    // 2 x 64 x 72
    __half* Vb = smh + 2 * TK * KLDH;    // 2 x 64 x 72

    int tid = threadIdx.x, warp = tid >> 5, lane = tid & 31;
    int g = lane >> 2, tau = lane & 3;

    int idx = blockIdx.x;
    int qblk = 15 - (idx >> 5);          // heavy blocks first
    int bh = idx & 31;
    int h = bh & 15, b = bh >> 4;
    int grp = h / HPG;
    int q0 = qblk * RQ;
    int ntiles = 2 * (qblk + 1);
    const float scale = 0.125f;

    const __half* KbaseH = K + (size_t)b * TT * KVD + grp * DH;
    const __half* VbaseH = V + (size_t)(b * NG + grp) * DH * TT;

    auto issue = [&](int kt) {
        int buf = kt & 1, kb = kt * TK;
        __half* kd = &Kb[buf * TK * KLDH];
        __half* vd = &Vb[buf * TK * KLDH];
        for (int i = tid; i < 512; i += 128) {
            int r = i >> 3, c = (i & 7) << 3;                 // 8 halves = 16B
            cp16(&kd[r * KLDH + c], KbaseH + (size_t)(kb + r) * KVD + c);
            cp16(&vd[r * KLDH + c], VbaseH + (size_t)r * TT + kb + c);
        }
        cp_commit();
    };
    issue(0);
    issue(1);

    // Q a-frags (fp16 m16n8k16 layout), loaded once from gmem.
    unsigned int qa[2][4][4];
#pragma unroll
    for (int m = 0; m < 2; m++) {
        const float* qp = Q + ((size_t)(b * TT + q0 + warp * 32 + m * 16)) * DM + h * DH;
#pragma unroll
        for (int c = 0; c < 4; c++) {
            float2 v0 = *(const float2*)(qp + (size_t)g * DM + c * 16 + 2 * tau);
            float2 v1 = *(const float2*)(qp + (size_t)(g + 8) * DM + c * 16 + 2 * tau);
            float2 v2 = *(const float2*)(qp + (size_t)g * DM + c * 16 + 8 + 2 * tau);
            float2 v3 = *(const float2*)(qp + (size_t)(g + 8) * DM + c * 16 + 8 + 2 * tau);
            qa[m][c][0] = pack_h2(v0.x * scale, v0.y * scale);
            qa[m][c][1] = pack_h2(v1.x * scale, v1.y * scale);
            qa[m][c][2] = pack_h2(v2.x * scale, v2.y * scale);
            qa[m][c][3] = pack_h2(v3.x * scale, v3.y * scale);
        }
    }

    float oc[2][8][4];
#pragma unroll
    for (int m = 0; m < 2; m++)
#pragma unroll
        for (int n = 0; n < 8; n++)
            oc[m][n][0] = oc[m][n][1] = oc[m][n][2] = oc[m][n][3] = 0.0f;
    float rsum[2][2];
    rsum[0][0] = rsum[0][1] = rsum[1][0] = rsum[1][1] = 0.0f;

    for (int kt = 0; kt < ntiles; kt++) {
        if (kt + 1 < ntiles) cp_wait<1>(); else cp_wait<0>();
        __syncthreads();
        const __half* Kt = &Kb[(kt & 1) * TK * KLDH];
        const __half* Vt = &Vb[(kt & 1) * TK * KLDH];
        bool need_mask = (kt >= 2 * qblk);
        int kcol = kt * TK;

#pragma unroll
        for (int jp = 0; jp < 4; jp++) {
            // S for j0 = 2*jp, j1 = 2*jp+1 (each 8 keys), k = 64 dh in 4 chunks
            float sa[2][2][4];
#pragma unroll
            for (int jj = 0; jj < 2; jj++)
#pragma unroll
                for (int m = 0; m < 2; m++)
                    sa[jj][m][0] = sa[jj][m][1] = sa[jj][m][2] = sa[jj][m][3] = 0.0f;
#pragma unroll
            for (int c = 0; c < 4; c++) {
#pragma unroll
                for (int jj = 0; jj < 2; jj++) {
                    const __half* krow = &Kt[((jp * 2 + jj) * 8 + g) * KLDH];
                    unsigned int b0 = *(const unsigned int*)(krow + c * 16 + 2 * tau);
                    unsigned int b1 = *(const unsigned int*)(krow + c * 16 + 8 + 2 * tau);
#pragma unroll
                    for (int m = 0; m < 2; m++)
                        mma_f16(sa[jj][m][0], sa[jj][m][1], sa[jj][m][2], sa[jj][m][3],
                                qa[m][c][0], qa[m][c][1], qa[m][c][2], qa[m][c][3],
                                b0, b1);
                }
            }

            // mask + exp + pack P into fp16 A-frags (zero shuffles)
            unsigned int af[2][4];
#pragma unroll
            for (int m = 0; m < 2; m++) {
                float p[2][4];
#pragma unroll
                for (int jj = 0; jj < 2; jj++) {
                    int j = jp * 2 + jj;
                    int row0 = q0 + warp * 32 + m * 16 + g;
                    int row1 = row0 + 8;
                    if (need_mask) {
                        int c = kcol + j * 8 + 2 * tau;
                        p[jj][0] = (c     <= row0) ? __expf(sa[jj][m][0]) : 0.0f;
                        p[jj][1] = (c + 1 <= row0) ? __expf(sa[jj][m][1]) : 0.0f;
                        p[jj][2] = (c     <= row1) ? __expf(sa[jj][m][2]) : 0.0f;
                        p[jj][3] = (c + 1 <= row1) ? __expf(sa[jj][m][3]) : 0.0f;
                    } else {
                        p[jj][0] = __expf(sa[jj][m][0]);
                        p[jj][1] = __expf(sa[jj][m][1]);
                        p[jj][2] = __expf(sa[jj][m][2]);
                        p[jj][3] = __expf(sa[jj][m][3]);
                    }
                    rsum[m][0] += p[jj][0] + p[jj][1];
                    rsum[m][1] += p[jj][2] + p[jj][3];
                }
                af[m][0] = pack_h2(p[0][0], p[0][1]);   // rows g,    keys jp16+2tau,+1
                af[m][1] = pack_h2(p[0][2], p[0][3]);   // rows g+8
                af[m][2] = pack_h2(p[1][0], p[1][1]);   // keys jp16+8+2tau,+1
                af[m][3] = pack_h2(p[1][2], p[1][3]);
            }

            // O += P[16q x 16keys] @ V[16keys x 64dh]  (V transposed in smem)
#pragma unroll
            for (int n = 0; n < 8; n++) {
                const __half* vrow = &Vt[(n * 8 + g) * KLDH];
                unsigned int b0 = *(const unsigned int*)(vrow + jp * 16 + 2 * tau);
                unsigned int b1 = *(const unsigned int*)(vrow + jp * 16 + 8 + 2 * tau);
#pragma unroll
                for (int m = 0; m < 2; m++)
                    mma_f16(oc[m][n][0], oc[m][n][1], oc[m][n][2], oc[m][n][3],
                            af[m][0], af[m][1], af[m][2], af[m][3], b0, b1);
            }
        }
        __syncthreads();
        if (kt + 2 < ntiles) issue(kt + 2);
    }

    // quad-reduce row sums, normalize, store (tf32-rounded for gemm_out)
#pragma unroll
    for (int m = 0; m < 2; m++) {
        float rs0 = rsum[m][0], rs1 = rsum[m][1];
        rs0 += __shfl_xor_sync(0xffffffffu, rs0, 1);
        rs0 += __shfl_xor_sync(0xffffffffu, rs0, 2);
        rs1 += __shfl_xor_sync(0xffffffffu, rs1, 1);
        rs1 += __shfl_xor_sync(0xffffffffu, rs1, 2);
        float inv0 = 1.0f / rs0, inv1 = 1.0f / rs1;
        int row0 = q0 + warp * 32 + m * 16 + g;
        float* o0 = O + ((size_t)(b * TT + row0)) * DM + h * DH + 2 * tau;
        float* o1 = O + ((size_t)(b * TT + row0 + 8)) * DM + h * DH + 2 * tau;
#pragma unroll
        for (int n = 0; n < 8; n++) {
            float2 v0, v1;
            v0.x = TF32(oc[m][n][0] * inv0); v0.y = TF32(oc[m][n][1] * inv0);
            v1.x = TF32(oc[m][n][2] * inv1); v1.y = TF32(oc[m][n][3] * inv1);
            *(float2*)(o0 + n * 8) = v0;
            *(float2*)(o1 + n * 8) = v1;
        }
    }
}

// ---------------------------------------------------------------------------
extern "C" void kernel_launch(void* const* d_in, const int* in_sizes, int n_in,
                              void* d_out, int out_size)
{
    const float* x  = (const float*)d_in[0];
    const float* Wq = (const float*)d_in[1];
    const float* bq = (const float*)d_in[2];
    const float* Wk = (const float*)d_in[3];
    const float* bk = (const float*)d_in[4];
    const float* Wv = (const float*)d_in[5];
    const float* bv = (const float*)d_in[6];
    const float* Wo = (const float*)d_in[7];
    const float* bo = (const float*)d_in[8];
    float* out = (float*)d_out;

    float *Q, *Kp, *Vp, *Ap, *Xr, *wqkv, *bqkv, *wo;
    __half *KpH, *VpH;
    cudaGetSymbolAddress((void**)&Q,    g_Q);
    cudaGetSymbolAddress((void**)&Kp,   g_K);
    cudaGetSymbolAddress((void**)&Vp,   g_V);
    cudaGetSymbolAddress((void**)&KpH,  g_KpH);
    cudaGetSymbolAddress((void**)&VpH,  g_VpH);
    cudaGetSymbolAddress((void**)&Ap,   g_A);
    cudaGetSymbolAddress((void**)&Xr,   g_X);
    cudaGetSymbolAddress((void**)&wqkv, g_Wqkv);
    cudaGetSymbolAddress((void**)&bqkv, g_bqkv);
    cudaGetSymbolAddress((void**)&wo,   g_Wo);

    cudaFuncSetAttribute((const void*)gemm_qkv_kernel,
                         cudaFuncAttributeMaxDynamicSharedMemorySize, GSMEM);
    cudaFuncSetAttribute((const void*)gemm_out_kernel,
                         cudaFuncAttributeMaxDynamicSharedMemorySize, GSMEM);
    cudaFuncSetAttribute((const void*)attn_f16_kernel,
                         cudaFuncAttributeMaxDynamicSharedMemorySize, ATT_SMEM);

    // prepass: round + pack (GEMM operands)
    prep_kernel<<<(N4_TOT + 255) / 256, 256>>>(x, Wq, Wk, Wv, Wo, bq, bk, bv,
                                               Xr, wqkv, wo, bqkv);

    // fused QKV projection
    dim3 gqkv(NQKV / 128, MTOT / 128);    // (12, 32)
    gemm_qkv_kernel<<<gqkv, 128, GSMEM>>>(Xr, wqkv, bqkv, Q, Kp, Vp);

    // rope Q in place; rope K -> fp16; transpose V -> fp16
    int nr = ROPE_NQ + ROPE_NK + VPERM_N;
    rope3_kernel<<<(nr + 255) / 256, 256>>>(Q, Kp, KpH, Vp, VpH);

    // fp16 attention
    attn_f16_kernel<<<512, 128, ATT_SMEM>>>(Q, KpH, VpH, Ap);

    // output projection
    dim3 go(DM / 128, MTOT / 128);        // (8, 32)
    gemm_out_kernel<<<go, 128, GSMEM>>>(Ap, wo, bo, out);
}

// round 14
// speedup vs baseline: 2.6469x; 2.2351x over previous
#include <cuda_runtime.h>
#include <cuda_fp16.h>
#include <cstdint>
#include <math.h>
#include <mma.h>

using namespace nvcuda;

// Problem constants
#define BB   2
#define TT   2048
#define DM   1024
#define NH   16
#define NG   4
#define DH   64
#define HPG  (NH / NG)          // 4
#define MTOT (BB * TT)          // 4096
#define KVD  (NG * DH)          // 256
#define NQKV (DM + 2 * KVD)     // 1536

// Scratch (no cudaMalloc allowed)
static __device__ float  g_Q[(size_t)MTOT * DM];
static __device__ float  g_K[(size_t)MTOT * KVD];
static __device__ float  g_V[(size_t)MTOT * KVD];
static __device__ __half g_KpH[(size_t)MTOT * KVD];   // rope'd fp16 [b][t][grp][d]
static __device__ __half g_VpH[(size_t)MTOT * KVD];   // fp16 transposed [b][grp][d][t]
static __device__ __half g_Ah[(size_t)MTOT * DM];     // attention out, fp16
static __device__ __half g_Xh  [(size_t)MTOT * DM];
static __device__ __half g_Wqkvh[(size_t)DM * NQKV];
static __device__ float  g_bqkv[NQKV];
static __device__ __half g_Woh [(size_t)DM * DM];

// ---------------------------------------------------------------------------
// helpers
// ---------------------------------------------------------------------------
__device__ __forceinline__ void cp16(void* s, const void* g) {
    unsigned int sa = (unsigned int)__cvta_generic_to_shared(s);
    asm volatile("cp.async.cg.shared.global [%0], [%1], 16;\n" :: "r"(sa), "l"(g));
}
__device__ __forceinline__ void cp_commit() { asm volatile("cp.async.commit_group;\n"); }
template<int N> __device__ __forceinline__ void cp_wait() {
    asm volatile("cp.async.wait_group %0;\n" :: "n"(N));
}

__device__ __forceinline__ unsigned int pack_h2(float a, float b) {
    __half2 h = __floats2half2_rn(a, b);
    return *(unsigned int*)&h;
}
__device__ __forceinline__ uint2 f4_to_h4(float4 v) {
    uint2 r;
    r.x = pack_h2(v.x, v.y);
    r.y = pack_h2(v.z, v.w);
    return r;
}

// mma.m16n8k16 f16: D(f32) += A(f16) * B(f16); A row-major, B col-major
__device__ __forceinline__ void mma_f16(
    float& d0, float& d1, float& d2, float& d3,
    unsigned int a0, unsigned int a1, unsigned int a2, unsigned int a3,
    unsigned int b0, unsigned int b1)
{
    asm volatile(
        "mma.sync.aligned.m16n8k16.row.col.f32.f16.f16.f32 "
        "{%0,%1,%2,%3}, {%4,%5,%6,%7}, {%8,%9}, {%0,%1,%2,%3};"
        : "+f"(d0), "+f"(d1), "+f"(d2), "+f"(d3)
        : "r"(a0), "r"(a1), "r"(a2), "r"(a3), "r"(b0), "r"(b1));
}

// ---------------------------------------------------------------------------
// prepass: convert GEMM operands to fp16; pack Wq|Wk|Wv; concat biases (fp32).
// ---------------------------------------------------------------------------
#define N4_X   (MTOT * DM / 4)
#define N4_QO  (DM * DM / 4)
#define N4_KV  (DM * KVD / 4)
#define N4_B   (NQKV / 4)
#define N4_TOT (N4_X + N4_QO + 2 * N4_KV + N4_QO + N4_B)

__global__ void prep_kernel(
    const float* __restrict__ x,  const float* __restrict__ Wq,
    const float* __restrict__ Wk, const float* __restrict__ Wv,
    const float* __restrict__ Wo,
    const float* __restrict__ bq, const float* __restrict__ bk,
    const float* __restrict__ bv,
    __half* __restrict__ Xh, __half* __restrict__ wqkv,
    __half* __restrict__ wo, float* __restrict__ bqkv)
{
    int i = blockIdx.x * blockDim.x + threadIdx.x;
    if (i >= N4_TOT) return;
    int off = i;
    if (off < N4_X) {
        ((uint2*)Xh)[off] = f4_to_h4(((const float4*)x)[off]);
        return;
    }
    off -= N4_X;
    if (off < N4_QO) {                        // Wq -> cols [0,1024)
        int r = off >> 8, c = off & 255;
        ((uint2*)wqkv)[r * (NQKV / 4) + c] = f4_to_h4(((const float4*)Wq)[off]);
        return;
    }
    off -= N4_QO;
    if (off < N4_KV) {                        // Wk -> cols [1024,1280)
        int r = off >> 6, c = off & 63;
        ((uint2*)wqkv)[r * (NQKV / 4) + 256 + c] = f4_to_h4(((const float4*)Wk)[off]);
        return;
    }
    off -= N4_KV;
    if (off < N4_KV) {                        // Wv -> cols [1280,1536)
        int r = off >> 6, c = off & 63;
        ((uint2*)wqkv)[r * (NQKV / 4) + 320 + c] = f4_to_h4(((const float4*)Wv)[off]);
        return;
    }
    off -= N4_KV;
    if (off < N4_QO) {
        ((uint2*)wo)[off] = f4_to_h4(((const float4*)Wo)[off]);
        return;
    }
    off -= N4_QO;
    float4 v;
    if (off < 256)      v = ((const float4*)bq)[off];
    else if (off < 320) v = ((const float4*)bk)[off - 256];
    else                v = ((const float4*)bv)[off - 320];
    ((float4*)bqkv)[off] = v;
}

// ---------------------------------------------------------------------------
// FP16 GEMM core: 128x128 tile, 4 warps (2x2 of 64x64), BK=32, 3-stage
// cp.async. fp16 operands, fp32 accumulate (wmma 16x16x16).
// ---------------------------------------------------------------------------
#define BKH  32
#define LDAH 40     // halves (multiple of 8)
#define LDBH 136    // halves
#define GSTH 3
#define GSMEMH ((GSTH * (128 * LDAH + BKH * LDBH)) * 2)   // 56832 B
#define LDBF 132    // fp32 bias staging row stride

template<typename EPI>
__device__ __forceinline__ void gemm_core_h(
    const __half* __restrict__ Ap, const __half* __restrict__ Bp, int ldbg,
    const float* __restrict__ biasp, EPI epi)
{
    extern __shared__ __half smh[];
    __half* As = smh;
    __half* Bs = smh + GSTH * 128 * LDAH;

    int tid = threadIdx.x;
    int warp = tid >> 5;
    int wm = warp & 1;
    int wn = warp >> 1;

    wmma::fragment<wmma::accumulator, 16, 16, 16, float> acc[4][4];

    // bias -> accumulators (fp32 staging in smem head)
    float* bstage = (float*)smh;
    for (int i = tid; i < 16 * 128; i += 128) {
        int r = i >> 7, c = i & 127;
        bstage[r * LDBF + c] = biasp[c];
    }
    __syncthreads();
#pragma unroll
    for (int i = 0; i < 4; i++)
#pragma unroll
        for (int j = 0; j < 4; j++)
            wmma::load_matrix_sync(acc[i][j], &bstage[wn * 64 + j * 16], LDBF,
                                   wmma::mem_row_major);
    __syncthreads();

    const int NIT = DM / BKH;   // 32

    auto issueG = [&](int it) {
        int s = it % GSTH, k0 = it * BKH;
        __half* as = &As[s * 128 * LDAH];
        __half* bs = &Bs[s * BKH * LDBH];
#pragma unroll
        for (int i = tid; i < 512; i += 128) {          // 128*32/8
            int r = i >> 2, c = (i & 3) << 3;
            cp16(&as[r * LDAH + c], Ap + (size_t)r * DM + k0 + c);
        }
#pragma unroll
        for (int i = tid; i < 512; i += 128) {          // 32*128/8
            int r = i >> 4, c = (i & 15) << 3;
            cp16(&bs[r * LDBH + c], Bp + (size_t)(k0 + r) * ldbg + c);
        }
        cp_commit();
    };

    issueG(0); issueG(1); issueG(2);

    for (int it = 0; it < NIT; it++) {
        if (it + 3 <= NIT) cp_wait<2>();
        else if (it + 2 <= NIT) cp_wait<1>();
        else cp_wait<0>();
        __syncthreads();
        int s = it % GSTH;
        const __half* as = &As[s * 128 * LDAH];
        const __half* bs = &Bs[s * BKH * LDBH];
#pragma unroll
        for (int ks = 0; ks < BKH; ks += 16) {
            wmma::fragment<wmma::matrix_a, 16, 16, 16, __half, wmma::row_major> af[4];
            wmma::fragment<wmma::matrix_b, 16, 16, 16, __half, wmma::row_major> bf[4];
#pragma unroll
            for (int i = 0; i < 4; i++)
                wmma::load_matrix_sync(af[i], &as[(wm * 64 + i * 16) * LDAH + ks], LDAH);
#pragma unroll
            for (int j = 0; j < 4; j++)
                wmma::load_matrix_sync(bf[j], &bs[ks * LDBH + wn * 64 + j * 16], LDBH);
#pragma unroll
            for (int i = 0; i < 4; i++)
#pragma unroll
                for (int j = 0; j < 4; j++)
                    wmma::mma_sync(acc[i][j], af[i], bf[j], acc[i][j]);
        }
        __syncthreads();
        if (it + GSTH < NIT) issueG(it + GSTH);
    }

    epi(acc, wm, wn);
}

// fused QKV GEMM: bn 0..7 -> Q, 8..9 -> K, 10..11 -> V (all fp32 out)
__global__ __launch_bounds__(128, 2) void gemm_qkv_kernel(
    const __half* __restrict__ A, const __half* __restrict__ Bw,
    const float* __restrict__ bias,
    float* __restrict__ Qo, float* __restrict__ Ko, float* __restrict__ Vo)
{
    int bn = blockIdx.x, bm = blockIdx.y;
    float* Cb; int ldc;
    if (bn < 8)       { Cb = Qo + bn * 128;          ldc = DM;  }
    else if (bn < 10) { Cb = Ko + (bn - 8) * 128;    ldc = KVD; }
    else              { Cb = Vo + (bn - 10) * 128;   ldc = KVD; }

    gemm_core_h(A + (size_t)bm * 128 * DM, Bw + bn * 128, NQKV, bias + bn * 128,
        [&](wmma::fragment<wmma::accumulator, 16, 16, 16, float> (&acc)[4][4],
            int wm, int wn) {
            float* Cp = Cb + (size_t)(bm * 128 + wm * 64) * ldc + wn * 64;
#pragma unroll
            for (int i = 0; i < 4; i++)
#pragma unroll
                for (int j = 0; j < 4; j++)
                    wmma::store_matrix_sync(Cp + (size_t)(i * 16) * ldc + j * 16,
                                            acc[i][j], ldc, wmma::mem_row_major);
        });
}

// output projection: out(f32) = Ah(f16) @ Woh(f16) + bo
__global__ __launch_bounds__(128, 2) void gemm_out_kernel(
    const __half* __restrict__ A, const __half* __restrict__ Bw,
    const float* __restrict__ bias, float* __restrict__ C)
{
    int bn = blockIdx.x, bm = blockIdx.y;
    gemm_core_h(A + (size_t)bm * 128 * DM, Bw + bn * 128, DM, bias + bn * 128,
        [&](wmma::fragment<wmma::accumulator, 16, 16, 16, float> (&acc)[4][4],
            int wm, int wn) {
            float* Cp = C + (size_t)(bm * 128 + wm * 64) * DM + bn * 128 + wn * 64;
#pragma unroll
            for (int i = 0; i < 4; i++)
#pragma unroll
                for (int j = 0; j < 4; j++)
                    wmma::store_matrix_sync(Cp + (size_t)(i * 16) * DM + j * 16,
                                            acc[i][j], DM, wmma::mem_row_major);
        });
}

// ---------------------------------------------------------------------------
// rope3: Q rope in place (fp32); K rope -> KpH (fp16, [b][t][grp][d]);
// V -> VpH (fp16, transposed [b][grp][d][t]). One launch.
// ---------------------------------------------------------------------------
#define ROPE_NQ (MTOT * NH * 32)
#define ROPE_NK (MTOT * NG * 32)
#define VPERM_N (MTOT * KVD)

__global__ void rope3_kernel(float* __restrict__ Qd,
                             const float* __restrict__ Kd, __half* __restrict__ Kp,
                             const float* __restrict__ Vd, __half* __restrict__ Vp)
{
    int idx = blockIdx.x * blockDim.x + threadIdx.x;
    if (idx < ROPE_NQ) {
        int i = idx & 31;
        int rest = idx >> 5;
        int t = (rest / NH) % TT;
        float freq = expf(-((2.0f * (float)i) / (float)DH) * 9.210340371976184f);
        float ang = (float)t * freq;
        float s, c;
        sincosf(ang, &s, &c);
        float* p = Qd + (size_t)rest * DH + 2 * i;
        float xe = p[0], xo = p[1];
        p[0] = xe * c - xo * s;
        p[1] = xe * s + xo * c;
        return;
    }
    idx -= ROPE_NQ;
    if (idx < ROPE_NK) {
        int i = idx & 31;
        int rest = idx >> 5;
        int t = (rest / NG) % TT;
        float freq = expf(-((2.0f * (float)i) / (float)DH) * 9.210340371976184f);
        float ang = (float)t * freq;
        float s, c;
        sincosf(ang, &s, &c);
        const float* p = Kd + (size_t)rest * DH + 2 * i;
        float xe = p[0], xo = p[1];
        Kp[(size_t)rest * DH + 2 * i]     = __float2half(xe * c - xo * s);
        Kp[(size_t)rest * DH + 2 * i + 1] = __float2half(xe * s + xo * c);
        return;
    }
    idx -= ROPE_NK;
    if (idx >= VPERM_N) return;
    // idx ordered [b][grp][d][t] for coalesced writes
    int t = idx & (TT - 1);
    int rest2 = idx >> 11;          // b*NG*DH + grp*DH + d
    int d = rest2 & (DH - 1);
    int bg = rest2 >> 6;            // b*NG + grp
    int b = bg >> 2, grp = bg & 3;
    float v = Vd[((size_t)(b * TT + t)) * KVD + grp * DH + d];
    Vp[idx] = __float2half(v);
}

// ---------------------------------------------------------------------------
// FP16 register-resident causal attention (FA2 zero-shuffle P conversion).
// 4 warps x 32 q-rows = RQ 128. Grid 512 heavy-first, 2 CTAs/SM.
// Output written fp16 to g_Ah.
// ---------------------------------------------------------------------------
#define RQ   128
#define TK   64
#define KLDH 72
#define ATT_SMEM (2 * 2 * TK * KLDH * 2)   // 36864 B

__global__ __launch_bounds__(128, 2) void attn_f16_kernel(
    const float* __restrict__ Q, const __half* __restrict__ K,
    const __half* __restrict__ V, __half* __restrict__ O)
{
    extern __shared__ __half smh[];
    __half* Kb = smh;                    // 2 x 64 x 72
    __half* Vb = smh + 2 * TK * KLDH;    // 2 x 64 x 72

    int tid = threadIdx.x, warp = tid >> 5, lane = tid & 31;
    int g = lane >> 2, tau = lane & 3;

    int idx = blockIdx.x;
    int qblk = 15 - (idx >> 5);          // heavy blocks first
    int bh = idx & 31;
    int h = bh & 15, b = bh >> 4;
    int grp = h / HPG;
    int q0 = qblk * RQ;
    int ntiles = 2 * (qblk + 1);
    const float scale = 0.125f;

    const __half* KbaseH = K + (size_t)b * TT * KVD + grp * DH;
    const __half* VbaseH = V + (size_t)(b * NG + grp) * DH * TT;

    auto issue = [&](int kt) {
        int buf = kt & 1, kb = kt * TK;
        __half* kd = &Kb[buf * TK * KLDH];
        __half* vd = &Vb[buf * TK * KLDH];
        for (int i = tid; i < 512; i += 128) {
            int r = i >> 3, c = (i & 7) << 3;
            cp16(&kd[r * KLDH + c], KbaseH + (size_t)(kb + r) * KVD + c);
            cp16(&vd[r * KLDH + c], VbaseH + (size_t)r * TT + kb + c);
        }
        cp_commit();
    };
    issue(0);
    issue(1);

    // Q a-frags (fp16 m16n8k16 layout), loaded once from gmem
    unsigned int qa[2][4][4];
#pragma unroll
    for (int m = 0; m < 2; m++) {
        const float* qp = Q + ((size_t)(b * TT + q0 + warp * 32 + m * 16)) * DM + h * DH;
#pragma unroll
        for (int c = 0; c < 4; c++) {
            float2 v0 = *(const float2*)(qp + (size_t)g * DM + c * 16 + 2 * tau);
            float2 v1 = *(const float2*)(qp + (size_t)(g + 8) * DM + c * 16 + 2 * tau);
            float2 v2 = *(const float2*)(qp + (size_t)g * DM + c * 16 + 8 + 2 * tau);
            float2 v3 = *(const float2*)(qp + (size_t)(g + 8) * DM + c * 16 + 8 + 2 * tau);
            qa[m][c][0] = pack_h2(v0.x * scale, v0.y * scale);
            qa[m][c][1] = pack_h2(v1.x * scale, v1.y * scale);
            qa[m][c][2] = pack_h2(v2.x * scale, v2.y * scale);
            qa[m][c][3] = pack_h2(v3.x * scale, v3.y * scale);
        }
    }

    float oc[2][8][4];
#pragma unroll
    for (int m = 0; m < 2; m++)
#pragma unroll
        for (int n = 0; n < 8; n++)
            oc[m][n][0] = oc[m][n][1] = oc[m][n][2] = oc[m][n][3] = 0.0f;
    float rsum[2][2];
    rsum[0][0] = rsum[0][1] = rsum[1][0] = rsum[1][1] = 0.0f;

    for (int kt = 0; kt < ntiles; kt++) {
        if (kt + 1 < ntiles) cp_wait<1>(); else cp_wait<0>();
        __syncthreads();
        const __half* Kt = &Kb[(kt & 1) * TK * KLDH];
        const __half* Vt = &Vb[(kt & 1) * TK * KLDH];
        bool need_mask = (kt >= 2 * qblk);
        int kcol = kt * TK;

#pragma unroll
        for (int jp = 0; jp < 4; jp++) {
            float sa[2][2][4];
#pragma unroll
            for (int jj = 0; jj < 2; jj++)
#pragma unroll
                for (int m = 0; m < 2; m++)
                    sa[jj][m][0] = sa[jj][m][1] = sa[jj][m][2] = sa[jj][m][3] = 0.0f;
#pragma unroll
            for (int c = 0; c < 4; c++) {
#pragma unroll
                for (int jj = 0; jj < 2; jj++) {
                    const __half* krow = &Kt[((jp * 2 + jj) * 8 + g) * KLDH];
                    unsigned int b0 = *(const unsigned int*)(krow + c * 16 + 2 * tau);
                    unsigned int b1 = *(const unsigned int*)(krow + c * 16 + 8 + 2 * tau);
#pragma unroll
                    for (int m = 0; m < 2; m++)
                        mma_f16(sa[jj][m][0], sa[jj][m][1], sa[jj][m][2], sa[jj][m][3],
                                qa[m][c][0], qa[m][c][1], qa[m][c][2], qa[m][c][3],
                                b0, b1);
                }
            }

            // mask + exp + pack P into fp16 A-frags (zero shuffles)
            unsigned int af[2][4];
#pragma unroll
            for (int m = 0; m < 2; m++) {
                float p[2][4];
#pragma unroll
                for (int jj = 0; jj < 2; jj++) {
                    int j = jp * 2 + jj;
                    int row0 = q0 + warp * 32 + m * 16 + g;
                    int row1 = row0 + 8;
                    if (need_mask) {
                        int c = kcol + j * 8 + 2 * tau;
                        p[jj][0] = (c     <= row0) ? __expf(sa[jj][m][0]) : 0.0f;
                        p[jj][1] = (c + 1 <= row0) ? __expf(sa[jj][m][1]) : 0.0f;
                        p[jj][2] = (c     <= row1) ? __expf(sa[jj][m][2]) : 0.0f;
                        p[jj][3] = (c + 1 <= row1) ? __expf(sa[jj][m][3]) : 0.0f;
                    } else {
                        p[jj][0] = __expf(sa[jj][m][0]);
                        p[jj][1] = __expf(sa[jj][m][1]);
                        p[jj][2] = __expf(sa[jj][m][2]);
                        p[jj][3] = __expf(sa[jj][m][3]);
                    }
                    rsum[m][0] += p[jj][0] + p[jj][1];
                    rsum[m][1] += p[jj][2] + p[jj][3];
                }
                af[m][0] = pack_h2(p[0][0], p[0][1]);
                af[m][1] = pack_h2(p[0][2], p[0][3]);
                af[m][2] = pack_h2(p[1][0], p[1][1]);
                af[m][3] = pack_h2(p[1][2], p[1][3]);
            }

            // O += P[16q x 16keys] @ V[16keys x 64dh]
#pragma unroll
            for (int n = 0; n < 8; n++) {
                const __half* vrow = &Vt[(n * 8 + g) * KLDH];
                unsigned int b0 = *(const unsigned int*)(vrow + jp * 16 + 2 * tau);
                unsigned int b1 = *(const unsigned int*)(vrow + jp * 16 + 8 + 2 * tau);
#pragma unroll
                for (int m = 0; m < 2; m++)
                    mma_f16(oc[m][n][0], oc[m][n][1], oc[m][n][2], oc[m][n][3],
                            af[m][0], af[m][1], af[m][2], af[m][3], b0, b1);
            }
        }
        __syncthreads();
        if (kt + 2 < ntiles) issue(kt + 2);
    }

    // quad-reduce row sums, normalize, store fp16
#pragma unroll
    for (int m = 0; m < 2; m++) {
        float rs0 = rsum[m][0], rs1 = rsum[m][1];
        rs0 += __shfl_xor_sync(0xffffffffu, rs0, 1);
        rs0 += __shfl_xor_sync(0xffffffffu, rs0, 2);
        rs1 += __shfl_xor_sync(0xffffffffu, rs1, 1);
        rs1 += __shfl_xor_sync(0xffffffffu, rs1, 2);
        float inv0 = 1.0f / rs0, inv1 = 1.0f / rs1;
        int row0 = q0 + warp * 32 + m * 16 + g;
        __half* o0 = O + ((size_t)(b * TT + row0)) * DM + h * DH + 2 * tau;
        __half* o1 = O + ((size_t)(b * TT + row0 + 8)) * DM + h * DH + 2 * tau;
#pragma unroll
        for (int n = 0; n < 8; n++) {
            *(unsigned int*)(o0 + n * 8) = pack_h2(oc[m][n][0] * inv0, oc[m][n][1] * inv0);
            *(unsigned int*)(o1 + n * 8) = pack_h2(oc[m][n][2] * inv1, oc[m][n][3] * inv1);
        }
    }
}

// ---------------------------------------------------------------------------
extern "C" void kernel_launch(void* const* d_in, const int* in_sizes, int n_in,
                              void* d_out, int out_size)
{
    const float* x  = (const float*)d_in[0];
    const float* Wq = (const float*)d_in[1];
    const float* bq = (const float*)d_in[2];
    const float* Wk = (const float*)d_in[3];
    const float* bk = (const float*)d_in[4];
    const float* Wv = (const float*)d_in[5];
    const float* bv = (const float*)d_in[6];
    const float* Wo = (const float*)d_in[7];
    const float* bo = (const float*)d_in[8];
    float* out = (float*)d_out;

    float *Q, *Kp, *Vp, *bqkv;
    __half *KpH, *VpH, *Ah, *Xh, *wqkvh, *woh;
    cudaGetSymbolAddress((void**)&Q,     g_Q);
    cudaGetSymbolAddress((void**)&Kp,    g_K);
    cudaGetSymbolAddress((void**)&Vp,    g_V);
    cudaGetSymbolAddress((void**)&KpH,   g_KpH);
    cudaGetSymbolAddress((void**)&VpH,   g_VpH);
    cudaGetSymbolAddress((void**)&Ah,    g_Ah);
    cudaGetSymbolAddress((void**)&Xh,    g_Xh);
    cudaGetSymbolAddress((void**)&wqkvh, g_Wqkvh);
    cudaGetSymbolAddress((void**)&bqkv,  g_bqkv);
    cudaGetSymbolAddress((void**)&woh,   g_Woh);

    cudaFuncSetAttribute((const void*)gemm_qkv_kernel,
                         cudaFuncAttributeMaxDynamicSharedMemorySize, GSMEMH);
    cudaFuncSetAttribute((const void*)gemm_out_kernel,
                         cudaFuncAttributeMaxDynamicSharedMemorySize, GSMEMH);
    cudaFuncSetAttribute((const void*)attn_f16_kernel,
                         cudaFuncAttributeMaxDynamicSharedMemorySize, ATT_SMEM);

    // prepass: convert + pack (fp16 GEMM operands)
    prep_kernel<<<(N4_TOT + 255) / 256, 256>>>(x, Wq, Wk, Wv, Wo, bq, bk, bv,
                                               Xh, wqkvh, woh, bqkv);

    // fused QKV projection (fp16 operands, fp32 out)
    dim3 gqkv(NQKV / 128, MTOT / 128);    // (12, 32)
    gemm_qkv_kernel<<<gqkv, 128, GSMEMH>>>(Xh, wqkvh, bqkv, Q, Kp, Vp);

    // rope Q in place; rope K -> fp16; transpose V -> fp16
    int nr = ROPE_NQ + ROPE_NK + VPERM_N;
    rope3_kernel<<<(nr + 255) / 256, 256>>>(Q, Kp, KpH, Vp, VpH);

    // fp16 attention -> fp16 output
    attn_f16_kernel<<<512, 128, ATT_SMEM>>>(Q, KpH, VpH, Ah);

    // output projection (fp16 A/B, fp32 out)
    dim3 go(DM / 128, MTOT / 128);        // (8, 32)
    gemm_out_kernel<<<go, 128, GSMEMH>>>(Ah, woh, bo, out);
}

// round 15
// speedup vs baseline: 2.8813x; 1.0885x over previous
#include <cuda_runtime.h>
#include <cuda_fp16.h>
#include <cstdint>
#include <math.h>
#include <mma.h>

using namespace nvcuda;

// Problem constants
#define BB   2
#define TT   2048
#define DM   1024
#define NH   16
#define NG   4
#define DH   64
#define HPG  (NH / NG)          // 4
#define MTOT (BB * TT)          // 4096
#define KVD  (NG * DH)          // 256
#define NQKV (DM + 2 * KVD)     // 1536

// Scratch (no cudaMalloc allowed)
static __device__ float  g_Q[(size_t)MTOT * DM];
static __device__ float  g_K[(size_t)MTOT * KVD];
static __device__ float  g_V[(size_t)MTOT * KVD];
static __device__ __half g_KpH[(size_t)MTOT * KVD];   // rope'd fp16 [b][t][grp][d]
static __device__ __half g_VpH[(size_t)MTOT * KVD];   // fp16 transposed [b][grp][d][t]
static __device__ __half g_Ah[(size_t)MTOT * DM];     // attention out, fp16
static __device__ __half g_Xh  [(size_t)MTOT * DM];
static __device__ __half g_Wqkvh[(size_t)DM * NQKV];
static __device__ float  g_bqkv[NQKV];
static __device__ __half g_Woh [(size_t)DM * DM];

// ---------------------------------------------------------------------------
// helpers
// ---------------------------------------------------------------------------
__device__ __forceinline__ void cp16(void* s, const void* g) {
    unsigned int sa = (unsigned int)__cvta_generic_to_shared(s);
    asm volatile("cp.async.cg.shared.global [%0], [%1], 16;\n" :: "r"(sa), "l"(g));
}
__device__ __forceinline__ void cp_commit() { asm volatile("cp.async.commit_group;\n"); }
template<int N> __device__ __forceinline__ void cp_wait() {
    asm volatile("cp.async.wait_group %0;\n" :: "n"(N));
}

__device__ __forceinline__ unsigned int pack_h2(float a, float b) {
    __half2 h = __floats2half2_rn(a, b);
    return *(unsigned int*)&h;
}
__device__ __forceinline__ uint2 f4_to_h4(float4 v) {
    uint2 r;
    r.x = pack_h2(v.x, v.y);
    r.y = pack_h2(v.z, v.w);
    return r;
}
// exp2 of two fp16 values packed in one register (MUFU, 1 instr for 2 exps)
__device__ __forceinline__ unsigned int ex2_h2(unsigned int s) {
    unsigned int r;
    asm volatile("ex2.approx.f16x2 %0, %1;" : "=r"(r) : "r"(s));
    return r;
}

// mma.m16n8k16 f16: D(f32) += A(f16) * B(f16); A row-major, B col-major
__device__ __forceinline__ void mma_f16(
    float& d0, float& d1, float& d2, float& d3,
    unsigned int a0, unsigned int a1, unsigned int a2, unsigned int a3,
    unsigned int b0, unsigned int b1)
{
    asm volatile(
        "mma.sync.aligned.m16n8k16.row.col.f32.f16.f16.f32 "
        "{%0,%1,%2,%3}, {%4,%5,%6,%7}, {%8,%9}, {%0,%1,%2,%3};"
        : "+f"(d0), "+f"(d1), "+f"(d2), "+f"(d3)
        : "r"(a0), "r"(a1), "r"(a2), "r"(a3), "r"(b0), "r"(b1));
}

// ---------------------------------------------------------------------------
// prepass: convert GEMM operands to fp16; pack Wq|Wk|Wv; concat biases (fp32).
// ---------------------------------------------------------------------------
#define N4_X   (MTOT * DM / 4)
#define N4_QO  (DM * DM / 4)
#define N4_KV  (DM * KVD / 4)
#define N4_B   (NQKV / 4)
#define N4_TOT (N4_X + N4_QO + 2 * N4_KV + N4_QO + N4_B)

__global__ void prep_kernel(
    const float* __restrict__ x,  const float* __restrict__ Wq,
    const float* __restrict__ Wk, const float* __restrict__ Wv,
    const float* __restrict__ Wo,
    const float* __restrict__ bq, const float* __restrict__ bk,
    const float* __restrict__ bv,
    __half* __restrict__ Xh, __half* __restrict__ wqkv,
    __half* __restrict__ wo, float* __restrict__ bqkv)
{
    int i = blockIdx.x * blockDim.x + threadIdx.x;
    if (i >= N4_TOT) return;
    int off = i;
    if (off < N4_X) {
        ((uint2*)Xh)[off] = f4_to_h4(((const float4*)x)[off]);
        return;
    }
    off -= N4_X;
    if (off < N4_QO) {
        int r = off >> 8, c = off & 255;
        ((uint2*)wqkv)[r * (NQKV / 4) + c] = f4_to_h4(((const float4*)Wq)[off]);
        return;
    }
    off -= N4_QO;
    if (off < N4_KV) {
        int r = off >> 6, c = off & 63;
        ((uint2*)wqkv)[r * (NQKV / 4) + 256 + c] = f4_to_h4(((const float4*)Wk)[off]);
        return;
    }
    off -= N4_KV;
    if (off < N4_KV) {
        int r = off >> 6, c = off & 63;
        ((uint2*)wqkv)[r * (NQKV / 4) + 320 + c] = f4_to_h4(((const float4*)Wv)[off]);
        return;
    }
    off -= N4_KV;
    if (off < N4_QO) {
        ((uint2*)wo)[off] = f4_to_h4(((const float4*)Wo)[off]);
        return;
    }
    off -= N4_QO;
    float4 v;
    if (off < 256)      v = ((const float4*)bq)[off];
    else if (off < 320) v = ((const float4*)bk)[off - 256];
    else                v = ((const float4*)bv)[off - 320];
    ((float4*)bqkv)[off] = v;
}

// ---------------------------------------------------------------------------
// FP16 GEMM core (unchanged from R14): 128x128 tile, 4 warps, BK=32, 3-stage.
// ---------------------------------------------------------------------------
#define BKH  32
#define LDAH 40
#define LDBH 136
#define GSTH 3
#define GSMEMH ((GSTH * (128 * LDAH + BKH * LDBH)) * 2)
#define LDBF 132

template<typename EPI>
__device__ __forceinline__ void gemm_core_h(
    const __half* __restrict__ Ap, const __half* __restrict__ Bp, int ldbg,
    const float* __restrict__ biasp, EPI epi)
{
    extern __shared__ __half smh[];
    __half* As = smh;
    __half* Bs = smh + GSTH * 128 * LDAH;

    int tid = threadIdx.x;
    int warp = tid >> 5;
    int wm = warp & 1;
    int wn = warp >> 1;

    wmma::fragment<wmma::accumulator, 16, 16, 16, float> acc[4][4];

    float* bstage = (float*)smh;
    for (int i = tid; i < 16 * 128; i += 128) {
        int r = i >> 7, c = i & 127;
        bstage[r * LDBF + c] = biasp[c];
    }
    __syncthreads();
#pragma unroll
    for (int i = 0; i < 4; i++)
#pragma unroll
        for (int j = 0; j < 4; j++)
            wmma::load_matrix_sync(acc[i][j], &bstage[wn * 64 + j * 16], LDBF,
                                   wmma::mem_row_major);
    __syncthreads();

    const int NIT = DM / BKH;

    auto issueG = [&](int it) {
        int s = it % GSTH, k0 = it * BKH;
        __half* as = &As[s * 128 * LDAH];
        __half* bs = &Bs[s * BKH * LDBH];
#pragma unroll
        for (int i = tid; i < 512; i += 128) {
            int r = i >> 2, c = (i & 3) << 3;
            cp16(&as[r * LDAH + c], Ap + (size_t)r * DM + k0 + c);
        }
#pragma unroll
        for (int i = tid; i < 512; i += 128) {
            int r = i >> 4, c = (i & 15) << 3;
            cp16(&bs[r * LDBH + c], Bp + (size_t)(k0 + r) * ldbg + c);
        }
        cp_commit();
    };

    issueG(0); issueG(1); issueG(2);

    for (int it = 0; it < NIT; it++) {
        if (it + 3 <= NIT) cp_wait<2>();
        else if (it + 2 <= NIT) cp_wait<1>();
        else cp_wait<0>();
        __syncthreads();
        int s = it % GSTH;
        const __half* as = &As[s * 128 * LDAH];
        const __half* bs = &Bs[s * BKH * LDBH];
#pragma unroll
        for (int ks = 0; ks < BKH; ks += 16) {
            wmma::fragment<wmma::matrix_a, 16, 16, 16, __half, wmma::row_major> af[4];
            wmma::fragment<wmma::matrix_b, 16, 16, 16, __half, wmma::row_major> bf[4];
#pragma unroll
            for (int i = 0; i < 4; i++)
                wmma::load_matrix_sync(af[i], &as[(wm * 64 + i * 16) * LDAH + ks], LDAH);
#pragma unroll
            for (int j = 0; j < 4; j++)
                wmma::load_matrix_sync(bf[j], &bs[ks * LDBH + wn * 64 + j * 16], LDBH);
#pragma unroll
            for (int i = 0; i < 4; i++)
#pragma unroll
                for (int j = 0; j < 4; j++)
                    wmma::mma_sync(acc[i][j], af[i], bf[j], acc[i][j]);
        }
        __syncthreads();
        if (it + GSTH < NIT) issueG(it + GSTH);
    }

    epi(acc, wm, wn);
}

// fused QKV GEMM: bn 0..7 -> Q, 8..9 -> K, 10..11 -> V (all fp32 out)
__global__ __launch_bounds__(128, 2) void gemm_qkv_kernel(
    const __half* __restrict__ A, const __half* __restrict__ Bw,
    const float* __restrict__ bias,
    float* __restrict__ Qo, float* __restrict__ Ko, float* __restrict__ Vo)
{
    int bn = blockIdx.x, bm = blockIdx.y;
    float* Cb; int ldc;
    if (bn < 8)       { Cb = Qo + bn * 128;          ldc = DM;  }
    else if (bn < 10) { Cb = Ko + (bn - 8) * 128;    ldc = KVD; }
    else              { Cb = Vo + (bn - 10) * 128;   ldc = KVD; }

    gemm_core_h(A + (size_t)bm * 128 * DM, Bw + bn * 128, NQKV, bias + bn * 128,
        [&](wmma::fragment<wmma::accumulator, 16, 16, 16, float> (&acc)[4][4],
            int wm, int wn) {
            float* Cp = Cb + (size_t)(bm * 128 + wm * 64) * ldc + wn * 64;
#pragma unroll
            for (int i = 0; i < 4; i++)
#pragma unroll
                for (int j = 0; j < 4; j++)
                    wmma::store_matrix_sync(Cp + (size_t)(i * 16) * ldc + j * 16,
                                            acc[i][j], ldc, wmma::mem_row_major);
        });
}

// output projection: out(f32) = Ah(f16) @ Woh(f16) + bo
__global__ __launch_bounds__(128, 2) void gemm_out_kernel(
    const __half* __restrict__ A, const __half* __restrict__ Bw,
    const float* __restrict__ bias, float* __restrict__ C)
{
    int bn = blockIdx.x, bm = blockIdx.y;
    gemm_core_h(A + (size_t)bm * 128 * DM, Bw + bn * 128, DM, bias + bn * 128,
        [&](wmma::fragment<wmma::accumulator, 16, 16, 16, float> (&acc)[4][4],
            int wm, int wn) {
            float* Cp = C + (size_t)(bm * 128 + wm * 64) * DM + bn * 128 + wn * 64;
#pragma unroll
            for (int i = 0; i < 4; i++)
#pragma unroll
                for (int j = 0; j < 4; j++)
                    wmma::store_matrix_sync(Cp + (size_t)(i * 16) * DM + j * 16,
                                            acc[i][j], DM, wmma::mem_row_major);
        });
}

// ---------------------------------------------------------------------------
// rope3: Q rope in place (fp32); K rope -> KpH (fp16); V -> VpH (fp16,
// transposed [b][grp][d][t]). One launch.
// ---------------------------------------------------------------------------
#define ROPE_NQ (MTOT * NH * 32)
#define ROPE_NK (MTOT * NG * 32)
#define VPERM_N (MTOT * KVD)

__global__ void rope3_kernel(float* __restrict__ Qd,
                             const float* __restrict__ Kd, __half* __restrict__ Kp,
                             const float* __restrict__ Vd, __half* __restrict__ Vp)
{
    int idx = blockIdx.x * blockDim.x + threadIdx.x;
    if (idx < ROPE_NQ) {
        int i = idx & 31;
        int rest = idx >> 5;
        int t = (rest / NH) % TT;
        float freq = expf(-((2.0f * (float)i) / (float)DH) * 9.210340371976184f);
        float ang = (float)t * freq;
        float s, c;
        sincosf(ang, &s, &c);
        float* p = Qd + (size_t)rest * DH + 2 * i;
        float xe = p[0], xo = p[1];
        p[0] = xe * c - xo * s;
        p[1] = xe * s + xo * c;
        return;
    }
    idx -= ROPE_NQ;
    if (idx < ROPE_NK) {
        int i = idx & 31;
        int rest = idx >> 5;
        int t = (rest / NG) % TT;
        float freq = expf(-((2.0f * (float)i) / (float)DH) * 9.210340371976184f);
        float ang = (float)t * freq;
        float s, c;
        sincosf(ang, &s, &c);
        const float* p = Kd + (size_t)rest * DH + 2 * i;
        float xe = p[0], xo = p[1];
        Kp[(size_t)rest * DH + 2 * i]     = __float2half(xe * c - xo * s);
        Kp[(size_t)rest * DH + 2 * i + 1] = __float2half(xe * s + xo * c);
        return;
    }
    idx -= ROPE_NK;
    if (idx >= VPERM_N) return;
    int t = idx & (TT - 1);
    int rest2 = idx >> 11;
    int d = rest2 & (DH - 1);
    int bg = rest2 >> 6;
    int b = bg >> 2, grp = bg & 3;
    float v = Vd[((size_t)(b * TT + t)) * KVD + grp * DH + d];
    Vp[idx] = __float2half(v);
}

// ---------------------------------------------------------------------------
// FP16 attention: ex2.f16x2 softmax (log2e folded into Q scale) + ones-column
// row sums via tensor core. 4 warps x 32 q-rows. Grid 512 heavy-first.
// V smem has 72 dh-rows: 0..63 data, 64 = ones (row-sum column), 65..71 zero.
// ---------------------------------------------------------------------------
#define RQ   128
#define TK   64
#define KLDH 72
#define VROWS 72
#define ATT_SMEM ((2 * TK * KLDH + 2 * VROWS * KLDH) * 2)   // 38016 B

__global__ __launch_bounds__(128, 2) void attn_f16_kernel(
    const float* __restrict__ Q, const __half* __restrict__ K,
    const __half* __restrict__ V, __half* __restrict__ O)
{
    extern __shared__ __half smh[];
    __half* Kb = smh;                    // 2 x 64 x 72
    __half* Vb = smh + 2 * TK * KLDH;    // 2 x 72 x 72

    int tid = threadIdx.x, warp = tid >> 5, lane = tid & 31;
    int g = lane >> 2, tau = lane & 3;

    int idx = blockIdx.x;
    int qblk = 15 - (idx >> 5);          // heavy blocks first
    int bh = idx & 31;
    int h = bh & 15, b = bh >> 4;
    int grp = h / HPG;
    int q0 = qblk * RQ;
    int ntiles = 2 * (qblk + 1);
    const float scale = 0.125f * 1.4426950408889634f;   // 1/sqrt(dh) * log2(e)

    const __half* KbaseH = K + (size_t)b * TT * KVD + grp * DH;
    const __half* VbaseH = V + (size_t)(b * NG + grp) * DH * TT;

    auto issue = [&](int kt) {
        int buf = kt & 1, kb = kt * TK;
        __half* kd = &Kb[buf * TK * KLDH];
        __half* vd = &Vb[buf * VROWS * KLDH];
        for (int i = tid; i < 512; i += 128) {
            int r = i >> 3, c = (i & 7) << 3;
            cp16(&kd[r * KLDH + c], KbaseH + (size_t)(kb + r) * KVD + c);
            cp16(&vd[r * KLDH + c], VbaseH + (size_t)r * TT + kb + c);
        }
        cp_commit();
    };
    issue(0);
    issue(1);

    // init V rows 64..71 for both buffers: row 64 = ones, 65..71 = zeros
    for (int i = tid; i < 2 * 8 * KLDH; i += 128) {
        int buf = i / (8 * KLDH), rem = i % (8 * KLDH);
        int r = 64 + rem / KLDH, c = rem % KLDH;
        Vb[buf * VROWS * KLDH + r * KLDH + c] =
            (r == 64) ? __float2half(1.0f) : __float2half(0.0f);
    }

    // Q a-frags (fp16 m16n8k16 layout), loaded once from gmem
    unsigned int qa[2][4][4];
#pragma unroll
    for (int m = 0; m < 2; m++) {
        const float* qp = Q + ((size_t)(b * TT + q0 + warp * 32 + m * 16)) * DM + h * DH;
#pragma unroll
        for (int c = 0; c < 4; c++) {
            float2 v0 = *(const float2*)(qp + (size_t)g * DM + c * 16 + 2 * tau);
            float2 v1 = *(const float2*)(qp + (size_t)(g + 8) * DM + c * 16 + 2 * tau);
            float2 v2 = *(const float2*)(qp + (size_t)g * DM + c * 16 + 8 + 2 * tau);
            float2 v3 = *(const float2*)(qp + (size_t)(g + 8) * DM + c * 16 + 8 + 2 * tau);
            qa[m][c][0] = pack_h2(v0.x * scale, v0.y * scale);
            qa[m][c][1] = pack_h2(v1.x * scale, v1.y * scale);
            qa[m][c][2] = pack_h2(v2.x * scale, v2.y * scale);
            qa[m][c][3] = pack_h2(v3.x * scale, v3.y * scale);
        }
    }

    // oc[m][0..7] = output dh blocks; oc[m][8] col 0 = row sums (ones column)
    float oc[2][9][4];
#pragma unroll
    for (int m = 0; m < 2; m++)
#pragma unroll
        for (int n = 0; n < 9; n++)
            oc[m][n][0] = oc[m][n][1] = oc[m][n][2] = oc[m][n][3] = 0.0f;

    for (int kt = 0; kt < ntiles; kt++) {
        if (kt + 1 < ntiles) cp_wait<1>(); else cp_wait<0>();
        __syncthreads();
        const __half* Kt = &Kb[(kt & 1) * TK * KLDH];
        const __half* Vt = &Vb[(kt & 1) * VROWS * KLDH];
        bool need_mask = (kt >= 2 * qblk);
        int kcol = kt * TK;

#pragma unroll
        for (int jp = 0; jp < 4; jp++) {
            float sa[2][2][4];
#pragma unroll
            for (int jj = 0; jj < 2; jj++)
#pragma unroll
                for (int m = 0; m < 2; m++)
                    sa[jj][m][0] = sa[jj][m][1] = sa[jj][m][2] = sa[jj][m][3] = 0.0f;
#pragma unroll
            for (int c = 0; c < 4; c++) {
#pragma unroll
                for (int jj = 0; jj < 2; jj++) {
                    const __half* krow = &Kt[((jp * 2 + jj) * 8 + g) * KLDH];
                    unsigned int b0 = *(const unsigned int*)(krow + c * 16 + 2 * tau);
                    unsigned int b1 = *(const unsigned int*)(krow + c * 16 + 8 + 2 * tau);
#pragma unroll
                    for (int m = 0; m < 2; m++)
                        mma_f16(sa[jj][m][0], sa[jj][m][1], sa[jj][m][2], sa[jj][m][3],
                                qa[m][c][0], qa[m][c][1], qa[m][c][2], qa[m][c][3],
                                b0, b1);
                }
            }

            // mask + pack + ex2.f16x2 (p = 2^(log2e * s) = e^s); zero shuffles
            unsigned int af[2][4];
#pragma unroll
            for (int m = 0; m < 2; m++) {
#pragma unroll
                for (int jj = 0; jj < 2; jj++) {
                    float s0 = sa[jj][m][0], s1 = sa[jj][m][1];
                    float s2 = sa[jj][m][2], s3 = sa[jj][m][3];
                    if (need_mask) {
                        int j = jp * 2 + jj;
                        int c = kcol + j * 8 + 2 * tau;
                        int row0 = q0 + warp * 32 + m * 16 + g;
                        int row1 = row0 + 8;
                        if (c     > row0) s0 = -INFINITY;
                        if (c + 1 > row0) s1 = -INFINITY;
                        if (c     > row1) s2 = -INFINITY;
                        if (c + 1 > row1) s3 = -INFINITY;
                    }
                    af[m][jj * 2 + 0] = ex2_h2(pack_h2(s0, s1));
                    af[m][jj * 2 + 1] = ex2_h2(pack_h2(s2, s3));
                }
            }

            // O += P @ [V ; ones]: n=0..7 output, n=8 row sums
#pragma unroll
            for (int n = 0; n < 9; n++) {
                const __half* vrow = &Vt[(n * 8 + g) * KLDH];
                unsigned int b0 = *(const unsigned int*)(vrow + jp * 16 + 2 * tau);
                unsigned int b1 = *(const unsigned int*)(vrow + jp * 16 + 8 + 2 * tau);
#pragma unroll
                for (int m = 0; m < 2; m++)
                    mma_f16(oc[m][n][0], oc[m][n][1], oc[m][n][2], oc[m][n][3],
                            af[m][0], af[m][1], af[m][2], af[m][3], b0, b1);
            }
        }
        __syncthreads();
        if (kt + 2 < ntiles) issue(kt + 2);
    }

    // row sums live in oc[m][8] (dh col 64 -> lanes tau==0); broadcast in quad
#pragma unroll
    for (int m = 0; m < 2; m++) {
        float rs0 = __shfl_sync(0xffffffffu, oc[m][8][0], lane & ~3);
        float rs1 = __shfl_sync(0xffffffffu, oc[m][8][2], lane & ~3);
        float inv0 = 1.0f / rs0, inv1 = 1.0f / rs1;
        int row0 = q0 + warp * 32 + m * 16 + g;
        __half* o0 = O + ((size_t)(b * TT + row0)) * DM + h * DH + 2 * tau;
        __half* o1 = O + ((size_t)(b * TT + row0 + 8)) * DM + h * DH + 2 * tau;
#pragma unroll
        for (int n = 0; n < 8; n++) {
            *(unsigned int*)(o0 + n * 8) = pack_h2(oc[m][n][0] * inv0, oc[m][n][1] * inv0);
            *(unsigned int*)(o1 + n * 8) = pack_h2(oc[m][n][2] * inv1, oc[m][n][3] * inv1);
        }
    }
}

// ---------------------------------------------------------------------------
extern "C" void kernel_launch(void* const* d_in, const int* in_sizes, int n_in,
                              void* d_out, int out_size)
{
    const float* x  = (const float*)d_in[0];
    const float* Wq = (const float*)d_in[1];
    const float* bq = (const float*)d_in[2];
    const float* Wk = (const float*)d_in[3];
    const float* bk = (const float*)d_in[4];
    const float* Wv = (const float*)d_in[5];
    const float* bv = (const float*)d_in[6];
    const float* Wo = (const float*)d_in[7];
    const float* bo = (const float*)d_in[8];
    float* out = (float*)d_out;

    float *Q, *Kp, *Vp, *bqkv;
    __half *KpH, *VpH, *Ah, *Xh, *wqkvh, *woh;
    cudaGetSymbolAddress((void**)&Q,     g_Q);
    cudaGetSymbolAddress((void**)&Kp,    g_K);
    cudaGetSymbolAddress((void**)&Vp,    g_V);
    cudaGetSymbolAddress((void**)&KpH,   g_KpH);
    cudaGetSymbolAddress((void**)&VpH,   g_VpH);
    cudaGetSymbolAddress((void**)&Ah,    g_Ah);
    cudaGetSymbolAddress((void**)&Xh,    g_Xh);
    cudaGetSymbolAddress((void**)&wqkvh, g_Wqkvh);
    cudaGetSymbolAddress((void**)&bqkv,  g_bqkv);
    cudaGetSymbolAddress((void**)&woh,   g_Woh);

    cudaFuncSetAttribute((const void*)gemm_qkv_kernel,
                         cudaFuncAttributeMaxDynamicSharedMemorySize, GSMEMH);
    cudaFuncSetAttribute((const void*)gemm_out_kernel,
                         cudaFuncAttributeMaxDynamicSharedMemorySize, GSMEMH);
    cudaFuncSetAttribute((const void*)attn_f16_kernel,
                         cudaFuncAttributeMaxDynamicSharedMemorySize, ATT_SMEM);

    // prepass: convert + pack (fp16 GEMM operands)
    prep_kernel<<<(N4_TOT + 255) / 256, 256>>>(x, Wq, Wk, Wv, Wo, bq, bk, bv,
                                               Xh, wqkvh, woh, bqkv);

    // fused QKV projection
    dim3 gqkv(NQKV / 128, MTOT / 128);    // (12, 32)
    gemm_qkv_kernel<<<gqkv, 128, GSMEMH>>>(Xh, wqkvh, bqkv, Q, Kp, Vp);

    // rope Q in place; rope K -> fp16; transpose V -> fp16
    int nr = ROPE_NQ + ROPE_NK + VPERM_N;
    rope3_kernel<<<(nr + 255) / 256, 256>>>(Q, Kp, KpH, Vp, VpH);

    // fp16 attention -> fp16 output
    attn_f16_kernel<<<512, 128, ATT_SMEM>>>(Q, KpH, VpH, Ah);

    // output projection
    dim3 go(DM / 128, MTOT / 128);        // (8, 32)
    gemm_out_kernel<<<go, 128, GSMEMH>>>(Ah, woh, bo, out);
}